// round 1
// baseline (speedup 1.0000x reference)
#include <cuda_runtime.h>
#include <cuda_bf16.h>
#include <math.h>

// Problem constants
#define BGRAPH 256
#define NNODE  256
#define DFEAT  128
#define KTOP   10
#define E_PER  8192
#define NUM_NODES (BGRAPH * NNODE)     // 65536
#define E_TOT (BGRAPH * E_PER)         // 2097152
#define OUT_CH 128
#define HALF_D 64

// ---------------- scratch (device globals; no runtime allocation) -------------
__device__ float g_bufA[NUM_NODES * DFEAT];
__device__ float g_bufB[NUM_NODES * DFEAT];
__device__ float g_od[NUM_NODES];
__device__ float g_id[NUM_NODES];
__device__ int   g_rowstart[NUM_NODES];   // global CSR start (b*E_PER + local)
__device__ int   g_cnt[NUM_NODES];        // in-degree (unclamped)
__device__ int   g_csr[E_TOT];            // local src index per in-edge (by dst)
__device__ float g_key[NUM_NODES];
__device__ int   g_topk[BGRAPH * KTOP];
__device__ float g_pooled[BGRAPH * KTOP * DFEAT];

// ---------------- kernel 1: degrees + isqrt + row offsets --------------------
__global__ void degrees_kernel(const int* __restrict__ src, const int* __restrict__ dst) {
    int b = blockIdx.x;
    int tid = threadIdx.x; // 256
    __shared__ int din[256], dout[256], scan[256];
    din[tid] = 0; dout[tid] = 0;
    __syncthreads();
    int ebase = b * E_PER;
    for (int e = tid; e < E_PER; e += 256) {
        atomicAdd(&dout[src[ebase + e] & 255], 1);
        atomicAdd(&din[dst[ebase + e] & 255], 1);
    }
    __syncthreads();
    int di = din[tid];
    int dou = dout[tid];
    int gn = b * NNODE + tid;
    g_od[gn] = 1.0f / sqrtf((float)max(dou, 1));
    g_id[gn] = 1.0f / sqrtf((float)max(di, 1));
    g_cnt[gn] = di;
    // inclusive scan of din (Hillis-Steele), then exclusive offset
    scan[tid] = di;
    __syncthreads();
    #pragma unroll
    for (int off = 1; off < 256; off <<= 1) {
        int v = (tid >= off) ? scan[tid - off] : 0;
        __syncthreads();
        scan[tid] += v;
        __syncthreads();
    }
    g_rowstart[gn] = ebase + scan[tid] - di;
}

// ---------------- kernel 2: deterministic CSR fill (warp per graph) ----------
__global__ void csr_fill_kernel(const int* __restrict__ src, const int* __restrict__ dst) {
    int w = threadIdx.x >> 5, lane = threadIdx.x & 31;
    int b = blockIdx.x * 8 + w;
    __shared__ int cur[8][256];
    for (int n = lane; n < 256; n += 32)
        cur[w][n] = g_rowstart[b * NNODE + n] - b * E_PER;
    __syncwarp();
    int ebase = b * E_PER;
    for (int c = 0; c < E_PER / 32; c++) {
        int e = ebase + c * 32 + lane;
        int d = dst[e] & 255;
        int s = src[e] & 255;
        unsigned mask = __match_any_sync(0xffffffffu, d);
        int rank = __popc(mask & ((1u << lane) - 1u));
        int base = cur[w][d];
        __syncwarp();
        g_csr[ebase + base + rank] = s;
        if (rank == 0) cur[w][d] = base + __popc(mask);
        __syncwarp();
    }
}

// ---------------- kernel 3: aggregation (block = one graph, one D-half) ------
// out[gn, half*64 + c] = id_isqrt[gn] * sum_{src in in(gn)} od_isqrt[src]*h[src, half*64+c]
__global__ void agg_kernel(const float* __restrict__ h_in, float* __restrict__ out) {
    extern __shared__ float sh[]; // 256 nodes * 64 floats = 64KB
    __shared__ float s_od[256];
    int b = blockIdx.x;
    int half = blockIdx.y;
    int tid = threadIdx.x; // 256
    int gbase = b * NNODE;

    if (tid < 256) s_od[tid] = g_od[gbase + tid];
    __syncthreads();

    // cooperative scaled load: 256 nodes x 16 float4
    for (int i4 = tid; i4 < NNODE * (HALF_D / 4); i4 += 256) {
        int n = i4 >> 4;
        int c4 = i4 & 15;
        float4 v = *(const float4*)&h_in[(gbase + n) * DFEAT + half * HALF_D + c4 * 4];
        float sc = s_od[n];
        v.x *= sc; v.y *= sc; v.z *= sc; v.w *= sc;
        *(float4*)&sh[n * HALF_D + c4 * 4] = v;
    }
    __syncthreads();

    int w = tid >> 5, lane = tid & 31;
    for (int n = w; n < NNODE; n += 8) {
        int gn = gbase + n;
        int rs = g_rowstart[gn];
        int cnt = g_cnt[gn];
        float2 acc = make_float2(0.f, 0.f);
        for (int base = 0; base < cnt; base += 32) {
            int nrem = min(32, cnt - base);
            int sl = (base + lane < cnt) ? g_csr[rs + base + lane] : 0;
            for (int j = 0; j < nrem; j++) {
                int s = __shfl_sync(0xffffffffu, sl, j);
                float2 v = *(const float2*)&sh[s * HALF_D + lane * 2];
                acc.x += v.x;
                acc.y += v.y;
            }
        }
        float iq = g_id[gn];
        acc.x *= iq; acc.y *= iq;
        *(float2*)&out[gn * DFEAT + half * HALF_D + lane * 2] = acc;
    }
}

// ---------------- kernel 4: fp32 GEMM + bias + relu --------------------------
// C[M,128] = relu(A[M,128] @ W[128,128] + bias)
__global__ void __launch_bounds__(256, 2) gemm_relu_kernel(
    const float* __restrict__ A, const float* __restrict__ W,
    const float* __restrict__ bias, float* __restrict__ C)
{
    __shared__ float sA[16][132]; // [k][m], padded
    __shared__ float sB[16][132]; // [k][n], padded
    int tid = threadIdx.x;      // 256
    int m0 = blockIdx.x * 128;
    int tx = tid & 15, ty = tid >> 4;
    float acc[8][8];
    #pragma unroll
    for (int i = 0; i < 8; i++)
        #pragma unroll
        for (int j = 0; j < 8; j++) acc[i][j] = 0.f;

    for (int k0 = 0; k0 < 128; k0 += 16) {
        // A tile 128 x 16 -> transposed store
        #pragma unroll
        for (int i = tid; i < 512; i += 256) {
            int m = i >> 2, v = i & 3;
            float4 a = *(const float4*)&A[(m0 + m) * 128 + k0 + v * 4];
            sA[v * 4 + 0][m] = a.x;
            sA[v * 4 + 1][m] = a.y;
            sA[v * 4 + 2][m] = a.z;
            sA[v * 4 + 3][m] = a.w;
        }
        // W tile 16 x 128, direct
        #pragma unroll
        for (int i = tid; i < 512; i += 256) {
            int k = i >> 5, v = i & 31;
            *(float4*)&sB[k][v * 4] = *(const float4*)&W[(k0 + k) * 128 + v * 4];
        }
        __syncthreads();
        #pragma unroll
        for (int k = 0; k < 16; k++) {
            float ar[8], br[8];
            *(float4*)&ar[0] = *(float4*)&sA[k][ty * 8];
            *(float4*)&ar[4] = *(float4*)&sA[k][ty * 8 + 4];
            *(float4*)&br[0] = *(float4*)&sB[k][tx * 8];
            *(float4*)&br[4] = *(float4*)&sB[k][tx * 8 + 4];
            #pragma unroll
            for (int i = 0; i < 8; i++)
                #pragma unroll
                for (int j = 0; j < 8; j++) acc[i][j] += ar[i] * br[j];
        }
        __syncthreads();
    }
    #pragma unroll
    for (int i = 0; i < 8; i++) {
        int m = m0 + ty * 8 + i;
        #pragma unroll
        for (int j4 = 0; j4 < 8; j4 += 4) {
            float4 v;
            v.x = fmaxf(acc[i][j4 + 0] + bias[tx * 8 + j4 + 0], 0.f);
            v.y = fmaxf(acc[i][j4 + 1] + bias[tx * 8 + j4 + 1], 0.f);
            v.z = fmaxf(acc[i][j4 + 2] + bias[tx * 8 + j4 + 2], 0.f);
            v.w = fmaxf(acc[i][j4 + 3] + bias[tx * 8 + j4 + 3], 0.f);
            *(float4*)&C[m * 128 + tx * 8 + j4] = v;
        }
    }
}

// ---------------- kernel 5: per-node row max (the sort key) ------------------
__global__ void key_kernel() {
    int gn = blockIdx.x * 8 + (threadIdx.x >> 5);
    int lane = threadIdx.x & 31;
    float4 v = *(const float4*)&g_bufB[gn * DFEAT + lane * 4];
    float m = fmaxf(fmaxf(v.x, v.y), fmaxf(v.z, v.w));
    #pragma unroll
    for (int off = 16; off; off >>= 1)
        m = fmaxf(m, __shfl_xor_sync(0xffffffffu, m, off));
    if (lane == 0) g_key[gn] = m;
}

// ---------------- kernel 6: top-k per graph (exact lax.top_k semantics) ------
__global__ void topk_kernel() {
    int w = threadIdx.x >> 5, lane = threadIdx.x & 31;
    int b = blockIdx.x * 8 + w;
    float v[8];
    #pragma unroll
    for (int r = 0; r < 8; r++) v[r] = g_key[b * NNODE + r * 32 + lane];
    for (int t = 0; t < KTOP; t++) {
        float bv = -INFINITY;
        int bi = 0;
        #pragma unroll
        for (int r = 0; r < 8; r++) {
            int idx = r * 32 + lane;
            if (v[r] > bv || (v[r] == bv && idx < bi)) { bv = v[r]; bi = idx; }
        }
        #pragma unroll
        for (int off = 16; off; off >>= 1) {
            float ov = __shfl_xor_sync(0xffffffffu, bv, off);
            int   oi = __shfl_xor_sync(0xffffffffu, bi, off);
            if (ov > bv || (ov == bv && oi < bi)) { bv = ov; bi = oi; }
        }
        if (lane == 0) g_topk[b * KTOP + t] = bi;
        if (lane == (bi & 31)) v[bi >> 5] = -INFINITY;
    }
}

// ---------------- kernel 7: sort the 2560 selected rows (ascending) ----------
__global__ void sort_rows_kernel() {
    int i = blockIdx.x;          // 0..2559
    int tid = threadIdx.x;       // 128
    __shared__ float s[128];
    int b = i / KTOP;
    int node = g_topk[i];
    s[tid] = g_bufB[(b * NNODE + node) * DFEAT + tid];
    __syncthreads();
    for (int k = 2; k <= 128; k <<= 1) {
        for (int j = k >> 1; j > 0; j >>= 1) {
            int p = tid ^ j;
            if (p > tid) {
                bool up = ((tid & k) == 0);
                float a = s[tid], c = s[p];
                if ((a > c) == up) { s[tid] = c; s[p] = a; }
            }
            __syncthreads();
        }
    }
    g_pooled[i * DFEAT + tid] = s[tid];
}

// ---------------- kernel 8: conv1 + maxpool + conv2 head ---------------------
__global__ void head_kernel(const float* __restrict__ w1, const float* __restrict__ b1c,
                            const float* __restrict__ w2, const float* __restrict__ b2c,
                            float* __restrict__ out)
{
    int b = blockIdx.x;
    int tid = threadIdx.x; // 128
    __shared__ float sp[KTOP][132];
    __shared__ float sw1[64][132];
    __shared__ float sc1[64][KTOP];
    __shared__ float sc1p[64][5];

    for (int i = tid; i < KTOP * DFEAT; i += 128)
        sp[i / DFEAT][i % DFEAT] = g_pooled[b * KTOP * DFEAT + i];
    for (int i = tid; i < 64 * DFEAT; i += 128)
        sw1[i / DFEAT][i % DFEAT] = w1[i];
    __syncthreads();

    // conv1: c1[oc][k] = relu(b1[oc] + dot(pooled[k], w1[oc]))
    for (int o = tid; o < 64 * KTOP; o += 128) {
        int oc = o / KTOP, k = o % KTOP;
        float acc = b1c[oc];
        #pragma unroll 8
        for (int d = 0; d < DFEAT; d++) acc += sp[k][d] * sw1[oc][d];
        sc1[oc][k] = fmaxf(acc, 0.f);
    }
    __syncthreads();
    // maxpool (window 2, stride 2)
    for (int o = tid; o < 64 * 5; o += 128) {
        int ic = o / 5, t = o % 5;
        sc1p[ic][t] = fmaxf(sc1[ic][2 * t], sc1[ic][2 * t + 1]);
    }
    __syncthreads();
    // conv2: out[oc2] = relu(b2[oc2] + sum_{ic,t} c1p[ic][t]*w2[oc2][ic][t])
    float acc = b2c[tid];
    const float* wrow = w2 + tid * 320;
    const float* cp = &sc1p[0][0];
    #pragma unroll 8
    for (int q = 0; q < 320; q++) acc += cp[q] * wrow[q];
    out[b * OUT_CH + tid] = fmaxf(acc, 0.f);
}

// ---------------- launcher ---------------------------------------------------
extern "C" void kernel_launch(void* const* d_in, const int* in_sizes, int n_in,
                              void* d_out, int out_size)
{
    const float* feats   = (const float*)d_in[0];
    const int*   src     = (const int*)d_in[1];
    const int*   dst     = (const int*)d_in[2];
    const float* W0      = (const float*)d_in[3];
    const float* b0      = (const float*)d_in[4];
    const float* W1      = (const float*)d_in[5];
    const float* b1      = (const float*)d_in[6];
    const float* W2      = (const float*)d_in[7];
    const float* b2      = (const float*)d_in[8];
    const float* conv1_w = (const float*)d_in[9];
    const float* conv1_b = (const float*)d_in[10];
    const float* conv2_w = (const float*)d_in[11];
    const float* conv2_b = (const float*)d_in[12];
    float* out = (float*)d_out;

    cudaFuncSetAttribute(agg_kernel, cudaFuncAttributeMaxDynamicSharedMemorySize, 65536);

    float* bufA;  cudaGetSymbolAddress((void**)&bufA, g_bufA);
    float* bufB;  cudaGetSymbolAddress((void**)&bufB, g_bufB);

    degrees_kernel<<<BGRAPH, 256>>>(src, dst);
    csr_fill_kernel<<<BGRAPH / 8, 256>>>(src, dst);

    dim3 agg_grid(BGRAPH, 2);
    // layer 0
    agg_kernel<<<agg_grid, 256, 65536>>>(feats, bufA);
    gemm_relu_kernel<<<NUM_NODES / 128, 256>>>(bufA, W0, b0, bufB);
    // layer 1
    agg_kernel<<<agg_grid, 256, 65536>>>(bufB, bufA);
    gemm_relu_kernel<<<NUM_NODES / 128, 256>>>(bufA, W1, b1, bufB);
    // layer 2
    agg_kernel<<<agg_grid, 256, 65536>>>(bufB, bufA);
    gemm_relu_kernel<<<NUM_NODES / 128, 256>>>(bufA, W2, b2, bufB);

    key_kernel<<<NUM_NODES / 8, 256>>>();
    topk_kernel<<<BGRAPH / 8, 256>>>();
    sort_rows_kernel<<<BGRAPH * KTOP, 128>>>();
    head_kernel<<<BGRAPH, 128>>>(conv1_w, conv1_b, conv2_w, conv2_b, out);
}

// round 3
// speedup vs baseline: 1.1297x; 1.1297x over previous
#include <cuda_runtime.h>
#include <cuda_bf16.h>
#include <math.h>

// Problem constants
#define BGRAPH 256
#define NNODE  256
#define DFEAT  128
#define KTOP   10
#define E_PER  8192
#define NUM_NODES (BGRAPH * NNODE)     // 65536
#define E_TOT (BGRAPH * E_PER)         // 2097152
#define OUT_CH 128
#define HALF_D 64
#define FULLMASK 0xffffffffu

// ---------------- scratch (device globals; no runtime allocation) -------------
__device__ float g_bufA[NUM_NODES * DFEAT];
__device__ float g_bufB[NUM_NODES * DFEAT];
__device__ float g_od[NUM_NODES];
__device__ float g_id[NUM_NODES];
__device__ int   g_rowstart[NUM_NODES];   // global CSR start (b*E_PER + local)
__device__ int   g_cnt[NUM_NODES];        // in-degree (unclamped)
__device__ int   g_csr[E_TOT];            // local src index per in-edge (by dst)
__device__ float g_key[NUM_NODES];
__device__ int   g_topk[BGRAPH * KTOP];
__device__ float g_pooled[BGRAPH * KTOP * DFEAT];

// =============================================================================
// kernel 1: merged graph build — degrees, isqrt, rowstarts, deterministic CSR.
// One block (256 thr = 8 warps) per graph. Warp w owns edge chunk
// [w*1024, (w+1)*1024). CSR order = global edge order (chunk-major, then
// in-chunk order), identical to a fully sequential fill => deterministic.
// =============================================================================
__global__ void build_kernel(const int* __restrict__ src, const int* __restrict__ dst) {
    int b = blockIdx.x;
    int tid = threadIdx.x;
    int w = tid >> 5, lane = tid & 31;
    __shared__ int cnts[8][256];   // per-warp-chunk dst histogram -> later prefix
    __shared__ int s_dout[256];
    __shared__ int scan[256];
    __shared__ int cur[8][256];

    for (int i = tid; i < 8 * 256; i += 256) ((int*)cnts)[i] = 0;
    s_dout[tid] = 0;
    __syncthreads();

    int ebase = b * E_PER;
    int wbase = ebase + w * 1024;
    for (int c = 0; c < 32; c++) {
        int e = wbase + c * 32 + lane;
        atomicAdd(&s_dout[src[e] & 255], 1);
        atomicAdd(&cnts[w][dst[e] & 255], 1);
    }
    __syncthreads();

    // per-dst: total in-degree + exclusive prefix of per-warp counts
    int t = tid;
    int run = 0;
    int pre[8];
    #pragma unroll
    for (int ww = 0; ww < 8; ww++) { pre[ww] = run; run += cnts[ww][t]; }
    int din = run;
    int gn = b * NNODE + t;
    g_cnt[gn] = din;
    g_id[gn] = 1.0f / sqrtf((float)max(din, 1));
    g_od[gn] = 1.0f / sqrtf((float)max(s_dout[t], 1));

    scan[t] = din;
    __syncthreads();
    #pragma unroll
    for (int off = 1; off < 256; off <<= 1) {
        int v = (t >= off) ? scan[t - off] : 0;
        __syncthreads();
        scan[t] += v;
        __syncthreads();
    }
    int rowlocal = scan[t] - din;
    g_rowstart[gn] = ebase + rowlocal;
    #pragma unroll
    for (int ww = 0; ww < 8; ww++) cur[ww][t] = rowlocal + pre[ww];
    __syncthreads();

    // fill phase: each warp fills its chunk in edge order
    for (int c = 0; c < 32; c++) {
        int e = wbase + c * 32 + lane;
        int d = dst[e] & 255;
        int s = src[e] & 255;
        unsigned mask = __match_any_sync(FULLMASK, d);
        int rank = __popc(mask & ((1u << lane) - 1u));
        int base = cur[w][d];
        __syncwarp();
        g_csr[ebase + base + rank] = s;
        if (rank == 0) cur[w][d] = base + __popc(mask);
        __syncwarp();
    }
}

// =============================================================================
// kernel 2: aggregation (block = one graph, one D-half), unrolled inner loop
// with 4 independent accumulator chains for ILP.
// =============================================================================
__global__ void agg_kernel(const float* __restrict__ h_in, float* __restrict__ out) {
    extern __shared__ float sh[]; // 256 nodes * 64 floats = 64KB
    __shared__ float s_od[256];
    int b = blockIdx.x;
    int half = blockIdx.y;
    int tid = threadIdx.x; // 256
    int gbase = b * NNODE;

    s_od[tid] = g_od[gbase + tid];
    __syncthreads();

    // cooperative scaled load: 256 nodes x 16 float4
    for (int i4 = tid; i4 < NNODE * (HALF_D / 4); i4 += 256) {
        int n = i4 >> 4;
        int c4 = i4 & 15;
        float4 v = *(const float4*)&h_in[(gbase + n) * DFEAT + half * HALF_D + c4 * 4];
        float sc = s_od[n];
        v.x *= sc; v.y *= sc; v.z *= sc; v.w *= sc;
        *(float4*)&sh[n * HALF_D + c4 * 4] = v;
    }
    __syncthreads();

    const float2* sh2 = (const float2*)sh;
    int w = tid >> 5, lane = tid & 31;
    for (int n = w; n < NNODE; n += 8) {
        int gn = gbase + n;
        int rs = g_rowstart[gn];
        int cnt = g_cnt[gn];
        float2 a0 = make_float2(0.f, 0.f), a1 = a0, a2 = a0, a3 = a0;
        for (int base = 0; base < cnt; base += 32) {
            int idx = base + lane;
            int sl = (idx < cnt) ? g_csr[rs + idx] : 0;   // 0 is a safe index
            int nrem = cnt - base;
            if (nrem >= 32) {
                #pragma unroll
                for (int j = 0; j < 32; j += 4) {
                    int s0 = __shfl_sync(FULLMASK, sl, j);
                    int s1 = __shfl_sync(FULLMASK, sl, j + 1);
                    int s2 = __shfl_sync(FULLMASK, sl, j + 2);
                    int s3 = __shfl_sync(FULLMASK, sl, j + 3);
                    float2 v0 = sh2[s0 * 32 + lane];
                    float2 v1 = sh2[s1 * 32 + lane];
                    float2 v2 = sh2[s2 * 32 + lane];
                    float2 v3 = sh2[s3 * 32 + lane];
                    a0.x += v0.x; a0.y += v0.y;
                    a1.x += v1.x; a1.y += v1.y;
                    a2.x += v2.x; a2.y += v2.y;
                    a3.x += v3.x; a3.y += v3.y;
                }
            } else {
                #pragma unroll
                for (int j = 0; j < 32; j += 4) {
                    if (j >= nrem) break;
                    int s0 = __shfl_sync(FULLMASK, sl, j);
                    int s1 = __shfl_sync(FULLMASK, sl, j + 1);
                    int s2 = __shfl_sync(FULLMASK, sl, j + 2);
                    int s3 = __shfl_sync(FULLMASK, sl, j + 3);
                    float2 v0 = sh2[s0 * 32 + lane];
                    float2 v1 = sh2[s1 * 32 + lane];
                    float2 v2 = sh2[s2 * 32 + lane];
                    float2 v3 = sh2[s3 * 32 + lane];
                    a0.x += v0.x; a0.y += v0.y;
                    if (j + 1 < nrem) { a1.x += v1.x; a1.y += v1.y; }
                    if (j + 2 < nrem) { a2.x += v2.x; a2.y += v2.y; }
                    if (j + 3 < nrem) { a3.x += v3.x; a3.y += v3.y; }
                }
            }
        }
        float iq = g_id[gn];
        float2 r;
        r.x = ((a0.x + a1.x) + (a2.x + a3.x)) * iq;
        r.y = ((a0.y + a1.y) + (a2.y + a3.y)) * iq;
        *(float2*)&out[gn * DFEAT + half * HALF_D + lane * 2] = r;
    }
}

// =============================================================================
// kernel 3: tf32 tensor-core GEMM + bias + relu  (3xTF32 split ~ fp32 accuracy)
// C[M,128] = relu(A[M,128] @ W[128,128] + bias)
// block: 256 thr = 8 warps (4x2), block tile 128x128, k-chunk 32.
// =============================================================================
__device__ __forceinline__ unsigned f2tf32(float x) {
    unsigned r;
    asm("cvt.rna.tf32.f32 %0, %1;" : "=r"(r) : "f"(x));
    return r;
}

#define MMA_TF32(d, a, b0, b1)                                                  \
    asm volatile("mma.sync.aligned.m16n8k8.row.col.f32.tf32.tf32.f32 "          \
                 "{%0,%1,%2,%3}, {%4,%5,%6,%7}, {%8,%9}, {%0,%1,%2,%3};\n"      \
                 : "+f"(d[0]), "+f"(d[1]), "+f"(d[2]), "+f"(d[3])               \
                 : "r"(a[0]), "r"(a[1]), "r"(a[2]), "r"(a[3]), "r"(b0), "r"(b1))

#define SROW 136   // padded smem row (floats) -> conflict-free fragment loads

__global__ void __launch_bounds__(256, 2) gemm_tc_kernel(
    const float* __restrict__ A, const float* __restrict__ W,
    const float* __restrict__ bias, float* __restrict__ C)
{
    extern __shared__ float smem[];
    float* sAh = smem;                 // [32][SROW] layout [k][m]
    float* sAl = sAh + 32 * SROW;
    float* sBh = sAl + 32 * SROW;     // [32][SROW] layout [k][n]
    float* sBl = sBh + 32 * SROW;
    __shared__ float sbias[128];

    int tid = threadIdx.x;
    int lane = tid & 31, warp = tid >> 5;
    int wm = warp >> 1, wn = warp & 1;   // warp tile: 32 (M) x 64 (N)
    int gid = lane >> 2, tig = lane & 3;
    int m0 = blockIdx.x * 128;

    if (tid < 128) sbias[tid] = bias[tid];

    float acc[2][8][4];
    #pragma unroll
    for (int mt = 0; mt < 2; mt++)
        #pragma unroll
        for (int nt = 0; nt < 8; nt++)
            #pragma unroll
            for (int q = 0; q < 4; q++) acc[mt][nt][q] = 0.f;

    int lm = tid >> 1;        // A row within tile  (0..127)
    int lh = tid & 1;         // A col half (16 cols each)
    int bk = tid >> 3;        // W row within chunk (0..31)
    int bg = tid & 7;         // W col group of 16

    for (int k0 = 0; k0 < 128; k0 += 32) {
        __syncthreads();
        // load+convert A chunk: 128 x 32, store transposed [k][m]
        const float* Ap = A + (m0 + lm) * 128 + k0 + lh * 16;
        #pragma unroll
        for (int q = 0; q < 4; q++) {
            float4 v = *(const float4*)(Ap + q * 4);
            int kb = lh * 16 + q * 4;
            float xs[4] = {v.x, v.y, v.z, v.w};
            #pragma unroll
            for (int e = 0; e < 4; e++) {
                unsigned hb = f2tf32(xs[e]);
                float hf = __uint_as_float(hb);
                unsigned lb = f2tf32(xs[e] - hf);
                sAh[(kb + e) * SROW + lm] = hf;
                sAl[(kb + e) * SROW + lm] = __uint_as_float(lb);
            }
        }
        // load+convert W chunk: 32 x 128, store [k][n]
        const float* Wp = W + (k0 + bk) * 128 + bg * 16;
        #pragma unroll
        for (int q = 0; q < 4; q++) {
            float4 v = *(const float4*)(Wp + q * 4);
            float xs[4] = {v.x, v.y, v.z, v.w};
            float4 hi4, lo4;
            float* hp = &hi4.x; float* lp = &lo4.x;
            #pragma unroll
            for (int e = 0; e < 4; e++) {
                unsigned hb = f2tf32(xs[e]);
                float hf = __uint_as_float(hb);
                hp[e] = hf;
                lp[e] = __uint_as_float(f2tf32(xs[e] - hf));
            }
            *(float4*)&sBh[bk * SROW + bg * 16 + q * 4] = hi4;
            *(float4*)&sBl[bk * SROW + bg * 16 + q * 4] = lo4;
        }
        __syncthreads();

        #pragma unroll
        for (int kk = 0; kk < 32; kk += 8) {
            unsigned ah[2][4], al[2][4];
            #pragma unroll
            for (int mt = 0; mt < 2; mt++) {
                int m = wm * 32 + mt * 16 + gid;
                int r0 = (kk + tig) * SROW + m;
                int r4 = (kk + tig + 4) * SROW + m;
                ah[mt][0] = __float_as_uint(sAh[r0]);
                ah[mt][1] = __float_as_uint(sAh[r0 + 8]);
                ah[mt][2] = __float_as_uint(sAh[r4]);
                ah[mt][3] = __float_as_uint(sAh[r4 + 8]);
                al[mt][0] = __float_as_uint(sAl[r0]);
                al[mt][1] = __float_as_uint(sAl[r0 + 8]);
                al[mt][2] = __float_as_uint(sAl[r4]);
                al[mt][3] = __float_as_uint(sAl[r4 + 8]);
            }
            #pragma unroll
            for (int nt = 0; nt < 8; nt++) {
                int n = wn * 64 + nt * 8 + gid;
                int c0 = (kk + tig) * SROW + n;
                int c4 = (kk + tig + 4) * SROW + n;
                unsigned bh0 = __float_as_uint(sBh[c0]);
                unsigned bh1 = __float_as_uint(sBh[c4]);
                unsigned bl0 = __float_as_uint(sBl[c0]);
                unsigned bl1 = __float_as_uint(sBl[c4]);
                MMA_TF32(acc[0][nt], ah[0], bh0, bh1);
                MMA_TF32(acc[1][nt], ah[1], bh0, bh1);
                MMA_TF32(acc[0][nt], al[0], bh0, bh1);
                MMA_TF32(acc[1][nt], al[1], bh0, bh1);
                MMA_TF32(acc[0][nt], ah[0], bl0, bl1);
                MMA_TF32(acc[1][nt], ah[1], bl0, bl1);
            }
        }
    }

    // epilogue: bias + relu, coalesced float2 stores
    #pragma unroll
    for (int mt = 0; mt < 2; mt++) {
        int r = m0 + wm * 32 + mt * 16 + gid;
        #pragma unroll
        for (int nt = 0; nt < 8; nt++) {
            int c = wn * 64 + nt * 8 + 2 * tig;
            float b0v = sbias[c], b1v = sbias[c + 1];
            float2 o0, o1;
            o0.x = fmaxf(acc[mt][nt][0] + b0v, 0.f);
            o0.y = fmaxf(acc[mt][nt][1] + b1v, 0.f);
            o1.x = fmaxf(acc[mt][nt][2] + b0v, 0.f);
            o1.y = fmaxf(acc[mt][nt][3] + b1v, 0.f);
            *(float2*)&C[r * 128 + c] = o0;
            *(float2*)&C[(r + 8) * 128 + c] = o1;
        }
    }
}

// ---------------- kernel 5: per-node row max (the sort key) ------------------
__global__ void key_kernel() {
    int gn = blockIdx.x * 8 + (threadIdx.x >> 5);
    int lane = threadIdx.x & 31;
    float4 v = *(const float4*)&g_bufB[gn * DFEAT + lane * 4];
    float m = fmaxf(fmaxf(v.x, v.y), fmaxf(v.z, v.w));
    #pragma unroll
    for (int off = 16; off; off >>= 1)
        m = fmaxf(m, __shfl_xor_sync(FULLMASK, m, off));
    if (lane == 0) g_key[gn] = m;
}

// ---------------- kernel 6: top-k per graph (exact lax.top_k semantics) ------
__global__ void topk_kernel() {
    int w = threadIdx.x >> 5, lane = threadIdx.x & 31;
    int b = blockIdx.x * 8 + w;
    float v[8];
    #pragma unroll
    for (int r = 0; r < 8; r++) v[r] = g_key[b * NNODE + r * 32 + lane];
    for (int t = 0; t < KTOP; t++) {
        float bv = -INFINITY;
        int bi = 0;
        #pragma unroll
        for (int r = 0; r < 8; r++) {
            int idx = r * 32 + lane;
            if (v[r] > bv || (v[r] == bv && idx < bi)) { bv = v[r]; bi = idx; }
        }
        #pragma unroll
        for (int off = 16; off; off >>= 1) {
            float ov = __shfl_xor_sync(FULLMASK, bv, off);
            int   oi = __shfl_xor_sync(FULLMASK, bi, off);
            if (ov > bv || (ov == bv && oi < bi)) { bv = ov; bi = oi; }
        }
        if (lane == 0) g_topk[b * KTOP + t] = bi;
        if (lane == (bi & 31)) v[bi >> 5] = -INFINITY;
    }
}

// ---------------- kernel 7: sort the 2560 selected rows (ascending) ----------
__global__ void sort_rows_kernel() {
    int i = blockIdx.x;          // 0..2559
    int tid = threadIdx.x;       // 128
    __shared__ float s[128];
    int b = i / KTOP;
    int node = g_topk[i];
    s[tid] = g_bufB[(b * NNODE + node) * DFEAT + tid];
    __syncthreads();
    for (int k = 2; k <= 128; k <<= 1) {
        for (int j = k >> 1; j > 0; j >>= 1) {
            int p = tid ^ j;
            if (p > tid) {
                bool up = ((tid & k) == 0);
                float a = s[tid], c = s[p];
                if ((a > c) == up) { s[tid] = c; s[p] = a; }
            }
            __syncthreads();
        }
    }
    g_pooled[i * DFEAT + tid] = s[tid];
}

// ---------------- kernel 8: conv1 + maxpool + conv2 head ---------------------
__global__ void head_kernel(const float* __restrict__ w1, const float* __restrict__ b1c,
                            const float* __restrict__ w2, const float* __restrict__ b2c,
                            float* __restrict__ out)
{
    int b = blockIdx.x;
    int tid = threadIdx.x; // 128
    __shared__ float sp[KTOP][132];
    __shared__ float sw1[64][132];
    __shared__ float sc1[64][KTOP];
    __shared__ float sc1p[64][5];

    for (int i = tid; i < KTOP * DFEAT; i += 128)
        sp[i / DFEAT][i % DFEAT] = g_pooled[b * KTOP * DFEAT + i];
    for (int i = tid; i < 64 * DFEAT; i += 128)
        sw1[i / DFEAT][i % DFEAT] = w1[i];
    __syncthreads();

    for (int o = tid; o < 64 * KTOP; o += 128) {
        int oc = o / KTOP, k = o % KTOP;
        float acc = b1c[oc];
        #pragma unroll 8
        for (int d = 0; d < DFEAT; d++) acc += sp[k][d] * sw1[oc][d];
        sc1[oc][k] = fmaxf(acc, 0.f);
    }
    __syncthreads();
    for (int o = tid; o < 64 * 5; o += 128) {
        int ic = o / 5, t = o % 5;
        sc1p[ic][t] = fmaxf(sc1[ic][2 * t], sc1[ic][2 * t + 1]);
    }
    __syncthreads();
    float acc = b2c[tid];
    const float* wrow = w2 + tid * 320;
    const float* cp = &sc1p[0][0];
    #pragma unroll 8
    for (int q = 0; q < 320; q++) acc += cp[q] * wrow[q];
    out[b * OUT_CH + tid] = fmaxf(acc, 0.f);
}

// ---------------- launcher ---------------------------------------------------
extern "C" void kernel_launch(void* const* d_in, const int* in_sizes, int n_in,
                              void* d_out, int out_size)
{
    const float* feats   = (const float*)d_in[0];
    const int*   src     = (const int*)d_in[1];
    const int*   dst     = (const int*)d_in[2];
    const float* W0      = (const float*)d_in[3];
    const float* b0      = (const float*)d_in[4];
    const float* W1      = (const float*)d_in[5];
    const float* b1      = (const float*)d_in[6];
    const float* W2      = (const float*)d_in[7];
    const float* b2      = (const float*)d_in[8];
    const float* conv1_w = (const float*)d_in[9];
    const float* conv1_b = (const float*)d_in[10];
    const float* conv2_w = (const float*)d_in[11];
    const float* conv2_b = (const float*)d_in[12];
    float* out = (float*)d_out;

    cudaFuncSetAttribute(agg_kernel, cudaFuncAttributeMaxDynamicSharedMemorySize, 65536);
    cudaFuncSetAttribute(gemm_tc_kernel, cudaFuncAttributeMaxDynamicSharedMemorySize, 4 * 32 * SROW * 4);

    float* bufA;  cudaGetSymbolAddress((void**)&bufA, g_bufA);
    float* bufB;  cudaGetSymbolAddress((void**)&bufB, g_bufB);

    build_kernel<<<BGRAPH, 256>>>(src, dst);

    dim3 agg_grid(BGRAPH, 2);
    int gemm_smem = 4 * 32 * SROW * 4;
    // layer 0
    agg_kernel<<<agg_grid, 256, 65536>>>(feats, bufA);
    gemm_tc_kernel<<<NUM_NODES / 128, 256, gemm_smem>>>(bufA, W0, b0, bufB);
    // layer 1
    agg_kernel<<<agg_grid, 256, 65536>>>(bufB, bufA);
    gemm_tc_kernel<<<NUM_NODES / 128, 256, gemm_smem>>>(bufA, W1, b1, bufB);
    // layer 2
    agg_kernel<<<agg_grid, 256, 65536>>>(bufB, bufA);
    gemm_tc_kernel<<<NUM_NODES / 128, 256, gemm_smem>>>(bufA, W2, b2, bufB);

    key_kernel<<<NUM_NODES / 8, 256>>>();
    topk_kernel<<<BGRAPH / 8, 256>>>();
    sort_rows_kernel<<<BGRAPH * KTOP, 128>>>();
    head_kernel<<<BGRAPH, 128>>>(conv1_w, conv1_b, conv2_w, conv2_b, out);
}

// round 4
// speedup vs baseline: 1.4167x; 1.2540x over previous
#include <cuda_runtime.h>
#include <cuda_bf16.h>
#include <math.h>

// Problem constants
#define BGRAPH 256
#define NNODE  256
#define DFEAT  128
#define KTOP   10
#define E_PER  8192
#define NUM_NODES (BGRAPH * NNODE)     // 65536
#define E_TOT (BGRAPH * E_PER)         // 2097152
#define OUT_CH 128
#define HALF_D 64
#define FULLMASK 0xffffffffu

// ---------------- scratch (device globals; no runtime allocation) -------------
__device__ float g_bufA[NUM_NODES * DFEAT];
__device__ float g_bufB[NUM_NODES * DFEAT];
__device__ float g_od[NUM_NODES];
__device__ float g_id[NUM_NODES];
__device__ __nv_bfloat16 g_adj[BGRAPH * NNODE * NNODE];  // 32 MB dense adjacency (integer counts)
__device__ float g_key[NUM_NODES];
__device__ int   g_topk[BGRAPH * KTOP];
__device__ float g_pooled[BGRAPH * KTOP * DFEAT];
__device__ float g_Whi[3 * DFEAT * DFEAT];
__device__ float g_Wlo[3 * DFEAT * DFEAT];

// =============================================================================
// kernel 1: graph build — zero dense Adj, edge-count atomics (bf16, exact for
// small ints -> order-independent -> deterministic), degree isqrt.
// One block (256 thr) per graph.
// =============================================================================
__global__ void build_kernel(const int* __restrict__ src, const int* __restrict__ dst) {
    int b = blockIdx.x;
    int tid = threadIdx.x;
    __shared__ int sdin[256], sdout[256];
    __nv_bfloat16* adjb = g_adj + b * (NNODE * NNODE);

    unsigned* az = (unsigned*)adjb;
    #pragma unroll 4
    for (int i = tid; i < NNODE * NNODE / 2; i += 256) az[i] = 0u;
    sdin[tid] = 0; sdout[tid] = 0;
    __syncthreads();

    int ebase = b * E_PER;
    const __nv_bfloat16 one = __float2bfloat16(1.0f);
    for (int e = tid; e < E_PER; e += 256) {
        int s = src[ebase + e] & 255;
        int d = dst[ebase + e] & 255;
        atomicAdd(&sdout[s], 1);
        atomicAdd(&sdin[d], 1);
        atomicAdd(adjb + d * NNODE + s, one);
    }
    __syncthreads();

    int gn = b * NNODE + tid;
    g_od[gn] = 1.0f / sqrtf((float)max(sdout[tid], 1));
    g_id[gn] = 1.0f / sqrtf((float)max(sdin[tid], 1));
}

// =============================================================================
// kernel 2: dense-adjacency aggregation via bf16 tensor cores.
// out[gbase+m, half*64+n] = id[m] * sum_s Adj[m][s] * od[s] * h[s][half*64+n]
// Block = (graph, half): M=256, N=64, K=256 (chunks of 64). 2-pass hi/lo on h.
// =============================================================================
#define MMA_BF16(d, a, b0v, b1v)                                                 \
    asm volatile("mma.sync.aligned.m16n8k16.row.col.f32.bf16.bf16.f32 "          \
                 "{%0,%1,%2,%3}, {%4,%5,%6,%7}, {%8,%9}, {%0,%1,%2,%3};\n"       \
                 : "+f"(d[0]), "+f"(d[1]), "+f"(d[2]), "+f"(d[3])                \
                 : "r"(a[0]), "r"(a[1]), "r"(a[2]), "r"(a[3]), "r"(b0v), "r"(b1v))

#define KPAD 72   // bf16 row stride: 144B -> 16B shift per row -> conflict-free

__global__ void __launch_bounds__(256, 2) agg_mma_kernel(
    const float* __restrict__ h_in, float* __restrict__ out)
{
    extern __shared__ __nv_bfloat16 sm[];
    __nv_bfloat16* sA  = sm;                 // [256][KPAD]  Adj chunk (rows=dst, cols=src)
    __nv_bfloat16* sBh = sm + 256 * KPAD;    // [64][KPAD]   feat-major (n-major) h hi
    __nv_bfloat16* sBl = sBh + 64 * KPAD;    // [64][KPAD]   h lo

    int b = blockIdx.x, half = blockIdx.y;
    int tid = threadIdx.x;
    int lane = tid & 31, warp = tid >> 5;
    int wm = warp >> 1, wn = warp & 1;       // warp tile 64(M) x 32(N)
    int g = lane >> 2, t = lane & 3;
    int gbase = b * NNODE;
    const __nv_bfloat16* adjb = g_adj + b * (NNODE * NNODE);

    float acc[4][4][4];
    #pragma unroll
    for (int mt = 0; mt < 4; mt++)
        #pragma unroll
        for (int nt = 0; nt < 4; nt++)
            #pragma unroll
            for (int q = 0; q < 4; q++) acc[mt][nt][q] = 0.f;

    for (int kc = 0; kc < 4; kc++) {
        int k0 = kc * 64;
        __syncthreads();
        // Adj chunk: 256 rows x 64 bf16 (128B per row = 8 uint4)
        #pragma unroll
        for (int i = tid; i < 2048; i += 256) {
            int r = i >> 3, q = i & 7;
            const uint4* s4 = (const uint4*)(adjb + r * NNODE + k0);
            *(uint4*)(sA + r * KPAD + q * 8) = s4[q];
        }
        // h chunk: 64 src-nodes x 64 feats, scale by od, split hi/lo, store n-major
        #pragma unroll
        for (int i = tid; i < 1024; i += 256) {
            int kk = i >> 4, f4 = i & 15;
            float od = __ldg(&g_od[gbase + k0 + kk]);
            float4 v = *(const float4*)&h_in[(gbase + k0 + kk) * DFEAT + half * HALF_D + f4 * 4];
            float xs[4] = {v.x * od, v.y * od, v.z * od, v.w * od};
            #pragma unroll
            for (int e = 0; e < 4; e++) {
                __nv_bfloat16 hi = __float2bfloat16(xs[e]);
                __nv_bfloat16 lo = __float2bfloat16(xs[e] - __bfloat162float(hi));
                sBh[(f4 * 4 + e) * KPAD + kk] = hi;
                sBl[(f4 * 4 + e) * KPAD + kk] = lo;
            }
        }
        __syncthreads();

        #pragma unroll
        for (int ks = 0; ks < 4; ks++) {
            int kk = ks * 16;
            unsigned a[4][4];
            #pragma unroll
            for (int mt = 0; mt < 4; mt++) {
                const __nv_bfloat16* pa = sA + (wm * 64 + mt * 16 + g) * KPAD + kk + 2 * t;
                a[mt][0] = *(const unsigned*)pa;
                a[mt][1] = *(const unsigned*)(pa + 8 * KPAD);
                a[mt][2] = *(const unsigned*)(pa + 8);
                a[mt][3] = *(const unsigned*)(pa + 8 * KPAD + 8);
            }
            #pragma unroll
            for (int nt = 0; nt < 4; nt++) {
                int nrow = wn * 32 + nt * 8 + g;
                const __nv_bfloat16* pbh = sBh + nrow * KPAD + kk + 2 * t;
                const __nv_bfloat16* pbl = sBl + nrow * KPAD + kk + 2 * t;
                unsigned bh0 = *(const unsigned*)pbh;
                unsigned bh1 = *(const unsigned*)(pbh + 8);
                unsigned bl0 = *(const unsigned*)pbl;
                unsigned bl1 = *(const unsigned*)(pbl + 8);
                #pragma unroll
                for (int mt = 0; mt < 4; mt++) {
                    MMA_BF16(acc[mt][nt], a[mt], bh0, bh1);
                    MMA_BF16(acc[mt][nt], a[mt], bl0, bl1);
                }
            }
        }
    }

    // epilogue: scale by id[dst], store
    #pragma unroll
    for (int mt = 0; mt < 4; mt++) {
        int m = wm * 64 + mt * 16 + g;
        float id0 = g_id[gbase + m];
        float id1 = g_id[gbase + m + 8];
        #pragma unroll
        for (int nt = 0; nt < 4; nt++) {
            int n = half * HALF_D + wn * 32 + nt * 8 + 2 * t;
            float2 o0, o1;
            o0.x = acc[mt][nt][0] * id0; o0.y = acc[mt][nt][1] * id0;
            o1.x = acc[mt][nt][2] * id1; o1.y = acc[mt][nt][3] * id1;
            *(float2*)&out[(gbase + m) * DFEAT + n] = o0;
            *(float2*)&out[(gbase + m + 8) * DFEAT + n] = o1;
        }
    }
}

// =============================================================================
// kernel 3: per-layer W hi/lo tf32 split (once, not per GEMM block)
// =============================================================================
__device__ __forceinline__ unsigned f2tf32(float x) {
    unsigned r;
    asm("cvt.rna.tf32.f32 %0, %1;" : "=r"(r) : "f"(x));
    return r;
}

__global__ void wsplit_kernel(const float* __restrict__ W, int layer) {
    int i = blockIdx.x * 256 + threadIdx.x;
    float x = W[i];
    unsigned hb = f2tf32(x);
    float hf = __uint_as_float(hb);
    g_Whi[layer * 16384 + i] = hf;
    g_Wlo[layer * 16384 + i] = __uint_as_float(f2tf32(x - hf));
}

// =============================================================================
// kernel 4: tf32 tensor-core GEMM + bias + relu  (3xTF32 split ~ fp32 accuracy)
// C[M,128] = relu(A[M,128] @ W[128,128] + bias); W pre-split in g_Whi/g_Wlo.
// =============================================================================
#define MMA_TF32(d, a, b0, b1)                                                  \
    asm volatile("mma.sync.aligned.m16n8k8.row.col.f32.tf32.tf32.f32 "          \
                 "{%0,%1,%2,%3}, {%4,%5,%6,%7}, {%8,%9}, {%0,%1,%2,%3};\n"      \
                 : "+f"(d[0]), "+f"(d[1]), "+f"(d[2]), "+f"(d[3])               \
                 : "r"(a[0]), "r"(a[1]), "r"(a[2]), "r"(a[3]), "r"(b0), "r"(b1))

#define SROW 136   // padded smem row (floats) -> conflict-free fragment loads

__global__ void __launch_bounds__(256, 2) gemm_tc_kernel(
    const float* __restrict__ A,
    const float* __restrict__ whi, const float* __restrict__ wlo,
    const float* __restrict__ bias, float* __restrict__ C)
{
    extern __shared__ float smem[];
    float* sAh = smem;                 // [32][SROW] layout [k][m]
    float* sAl = sAh + 32 * SROW;
    float* sBh = sAl + 32 * SROW;     // [32][SROW] layout [k][n]
    float* sBl = sBh + 32 * SROW;
    __shared__ float sbias[128];

    int tid = threadIdx.x;
    int lane = tid & 31, warp = tid >> 5;
    int wm = warp >> 1, wn = warp & 1;   // warp tile: 32 (M) x 64 (N)
    int gid = lane >> 2, tig = lane & 3;
    int m0 = blockIdx.x * 128;

    if (tid < 128) sbias[tid] = bias[tid];

    float acc[2][8][4];
    #pragma unroll
    for (int mt = 0; mt < 2; mt++)
        #pragma unroll
        for (int nt = 0; nt < 8; nt++)
            #pragma unroll
            for (int q = 0; q < 4; q++) acc[mt][nt][q] = 0.f;

    int lm = tid >> 1;        // A row within tile  (0..127)
    int lh = tid & 1;         // A col half (16 cols each)
    int bk = tid >> 3;        // W row within chunk (0..31)
    int bg = tid & 7;         // W col group of 16

    for (int k0 = 0; k0 < 128; k0 += 32) {
        __syncthreads();
        // load+convert A chunk: 128 x 32, store transposed [k][m]
        const float* Ap = A + (m0 + lm) * 128 + k0 + lh * 16;
        #pragma unroll
        for (int q = 0; q < 4; q++) {
            float4 v = *(const float4*)(Ap + q * 4);
            int kb = lh * 16 + q * 4;
            float xs[4] = {v.x, v.y, v.z, v.w};
            #pragma unroll
            for (int e = 0; e < 4; e++) {
                unsigned hb = f2tf32(xs[e]);
                float hf = __uint_as_float(hb);
                unsigned lb = f2tf32(xs[e] - hf);
                sAh[(kb + e) * SROW + lm] = hf;
                sAl[(kb + e) * SROW + lm] = __uint_as_float(lb);
            }
        }
        // W chunk: pre-split, plain float4 copies
        #pragma unroll
        for (int q = 0; q < 4; q++) {
            *(float4*)&sBh[bk * SROW + bg * 16 + q * 4] =
                *(const float4*)&whi[(k0 + bk) * 128 + bg * 16 + q * 4];
            *(float4*)&sBl[bk * SROW + bg * 16 + q * 4] =
                *(const float4*)&wlo[(k0 + bk) * 128 + bg * 16 + q * 4];
        }
        __syncthreads();

        #pragma unroll
        for (int kk = 0; kk < 32; kk += 8) {
            unsigned ah[2][4], al[2][4];
            #pragma unroll
            for (int mt = 0; mt < 2; mt++) {
                int m = wm * 32 + mt * 16 + gid;
                int r0 = (kk + tig) * SROW + m;
                int r4 = (kk + tig + 4) * SROW + m;
                ah[mt][0] = __float_as_uint(sAh[r0]);
                ah[mt][1] = __float_as_uint(sAh[r0 + 8]);
                ah[mt][2] = __float_as_uint(sAh[r4]);
                ah[mt][3] = __float_as_uint(sAh[r4 + 8]);
                al[mt][0] = __float_as_uint(sAl[r0]);
                al[mt][1] = __float_as_uint(sAl[r0 + 8]);
                al[mt][2] = __float_as_uint(sAl[r4]);
                al[mt][3] = __float_as_uint(sAl[r4 + 8]);
            }
            #pragma unroll
            for (int nt = 0; nt < 8; nt++) {
                int n = wn * 64 + nt * 8 + gid;
                int c0 = (kk + tig) * SROW + n;
                int c4 = (kk + tig + 4) * SROW + n;
                unsigned bh0 = __float_as_uint(sBh[c0]);
                unsigned bh1 = __float_as_uint(sBh[c4]);
                unsigned bl0 = __float_as_uint(sBl[c0]);
                unsigned bl1 = __float_as_uint(sBl[c4]);
                MMA_TF32(acc[0][nt], ah[0], bh0, bh1);
                MMA_TF32(acc[1][nt], ah[1], bh0, bh1);
                MMA_TF32(acc[0][nt], al[0], bh0, bh1);
                MMA_TF32(acc[1][nt], al[1], bh0, bh1);
                MMA_TF32(acc[0][nt], ah[0], bl0, bl1);
                MMA_TF32(acc[1][nt], ah[1], bl0, bl1);
            }
        }
    }

    // epilogue: bias + relu, coalesced float2 stores
    #pragma unroll
    for (int mt = 0; mt < 2; mt++) {
        int r = m0 + wm * 32 + mt * 16 + gid;
        #pragma unroll
        for (int nt = 0; nt < 8; nt++) {
            int c = wn * 64 + nt * 8 + 2 * tig;
            float b0v = sbias[c], b1v = sbias[c + 1];
            float2 o0, o1;
            o0.x = fmaxf(acc[mt][nt][0] + b0v, 0.f);
            o0.y = fmaxf(acc[mt][nt][1] + b1v, 0.f);
            o1.x = fmaxf(acc[mt][nt][2] + b0v, 0.f);
            o1.y = fmaxf(acc[mt][nt][3] + b1v, 0.f);
            *(float2*)&C[r * 128 + c] = o0;
            *(float2*)&C[(r + 8) * 128 + c] = o1;
        }
    }
}

// ---------------- kernel 5: per-node row max (the sort key) ------------------
__global__ void key_kernel() {
    int gn = blockIdx.x * 8 + (threadIdx.x >> 5);
    int lane = threadIdx.x & 31;
    float4 v = *(const float4*)&g_bufB[gn * DFEAT + lane * 4];
    float m = fmaxf(fmaxf(v.x, v.y), fmaxf(v.z, v.w));
    #pragma unroll
    for (int off = 16; off; off >>= 1)
        m = fmaxf(m, __shfl_xor_sync(FULLMASK, m, off));
    if (lane == 0) g_key[gn] = m;
}

// ---------------- kernel 6: top-k per graph (exact lax.top_k semantics) ------
__global__ void topk_kernel() {
    int w = threadIdx.x >> 5, lane = threadIdx.x & 31;
    int b = blockIdx.x * 8 + w;
    float v[8];
    #pragma unroll
    for (int r = 0; r < 8; r++) v[r] = g_key[b * NNODE + r * 32 + lane];
    for (int t = 0; t < KTOP; t++) {
        float bv = -INFINITY;
        int bi = 0;
        #pragma unroll
        for (int r = 0; r < 8; r++) {
            int idx = r * 32 + lane;
            if (v[r] > bv || (v[r] == bv && idx < bi)) { bv = v[r]; bi = idx; }
        }
        #pragma unroll
        for (int off = 16; off; off >>= 1) {
            float ov = __shfl_xor_sync(FULLMASK, bv, off);
            int   oi = __shfl_xor_sync(FULLMASK, bi, off);
            if (ov > bv || (ov == bv && oi < bi)) { bv = ov; bi = oi; }
        }
        if (lane == 0) g_topk[b * KTOP + t] = bi;
        if (lane == (bi & 31)) v[bi >> 5] = -INFINITY;
    }
}

// ---------------- kernel 7: sort the 2560 selected rows (ascending) ----------
__global__ void sort_rows_kernel() {
    int i = blockIdx.x;          // 0..2559
    int tid = threadIdx.x;       // 128
    __shared__ float s[128];
    int b = i / KTOP;
    int node = g_topk[i];
    s[tid] = g_bufB[(b * NNODE + node) * DFEAT + tid];
    __syncthreads();
    for (int k = 2; k <= 128; k <<= 1) {
        for (int j = k >> 1; j > 0; j >>= 1) {
            int p = tid ^ j;
            if (p > tid) {
                bool up = ((tid & k) == 0);
                float a = s[tid], c = s[p];
                if ((a > c) == up) { s[tid] = c; s[p] = a; }
            }
            __syncthreads();
        }
    }
    g_pooled[i * DFEAT + tid] = s[tid];
}

// ---------------- kernel 8: conv1 + maxpool + conv2 head ---------------------
__global__ void head_kernel(const float* __restrict__ w1, const float* __restrict__ b1c,
                            const float* __restrict__ w2, const float* __restrict__ b2c,
                            float* __restrict__ out)
{
    int b = blockIdx.x;
    int tid = threadIdx.x; // 128
    __shared__ float sp[KTOP][132];
    __shared__ float sw1[64][132];
    __shared__ float sc1[64][KTOP];
    __shared__ float sc1p[64][5];

    for (int i = tid; i < KTOP * DFEAT; i += 128)
        sp[i / DFEAT][i % DFEAT] = g_pooled[b * KTOP * DFEAT + i];
    for (int i = tid; i < 64 * DFEAT; i += 128)
        sw1[i / DFEAT][i % DFEAT] = w1[i];
    __syncthreads();

    for (int o = tid; o < 64 * KTOP; o += 128) {
        int oc = o / KTOP, k = o % KTOP;
        float acc = b1c[oc];
        #pragma unroll 8
        for (int d = 0; d < DFEAT; d++) acc += sp[k][d] * sw1[oc][d];
        sc1[oc][k] = fmaxf(acc, 0.f);
    }
    __syncthreads();
    for (int o = tid; o < 64 * 5; o += 128) {
        int ic = o / 5, t = o % 5;
        sc1p[ic][t] = fmaxf(sc1[ic][2 * t], sc1[ic][2 * t + 1]);
    }
    __syncthreads();
    float acc = b2c[tid];
    const float* wrow = w2 + tid * 320;
    const float* cp = &sc1p[0][0];
    #pragma unroll 8
    for (int q = 0; q < 320; q++) acc += cp[q] * wrow[q];
    out[b * OUT_CH + tid] = fmaxf(acc, 0.f);
}

// ---------------- launcher ---------------------------------------------------
extern "C" void kernel_launch(void* const* d_in, const int* in_sizes, int n_in,
                              void* d_out, int out_size)
{
    const float* feats   = (const float*)d_in[0];
    const int*   src     = (const int*)d_in[1];
    const int*   dst     = (const int*)d_in[2];
    const float* W0      = (const float*)d_in[3];
    const float* b0      = (const float*)d_in[4];
    const float* W1      = (const float*)d_in[5];
    const float* b1      = (const float*)d_in[6];
    const float* W2      = (const float*)d_in[7];
    const float* b2      = (const float*)d_in[8];
    const float* conv1_w = (const float*)d_in[9];
    const float* conv1_b = (const float*)d_in[10];
    const float* conv2_w = (const float*)d_in[11];
    const float* conv2_b = (const float*)d_in[12];
    float* out = (float*)d_out;

    int agg_smem = (256 * KPAD + 2 * 64 * KPAD) * (int)sizeof(__nv_bfloat16);  // 55296
    int gemm_smem = 4 * 32 * SROW * 4;
    cudaFuncSetAttribute(agg_mma_kernel, cudaFuncAttributeMaxDynamicSharedMemorySize, agg_smem);
    cudaFuncSetAttribute(gemm_tc_kernel, cudaFuncAttributeMaxDynamicSharedMemorySize, gemm_smem);

    float* bufA;  cudaGetSymbolAddress((void**)&bufA, g_bufA);
    float* bufB;  cudaGetSymbolAddress((void**)&bufB, g_bufB);
    float* whi;   cudaGetSymbolAddress((void**)&whi, g_Whi);
    float* wlo;   cudaGetSymbolAddress((void**)&wlo, g_Wlo);

    build_kernel<<<BGRAPH, 256>>>(src, dst);
    wsplit_kernel<<<64, 256>>>(W0, 0);
    wsplit_kernel<<<64, 256>>>(W1, 1);
    wsplit_kernel<<<64, 256>>>(W2, 2);

    dim3 agg_grid(BGRAPH, 2);
    // layer 0
    agg_mma_kernel<<<agg_grid, 256, agg_smem>>>(feats, bufA);
    gemm_tc_kernel<<<NUM_NODES / 128, 256, gemm_smem>>>(bufA, whi, wlo, b0, bufB);
    // layer 1
    agg_mma_kernel<<<agg_grid, 256, agg_smem>>>(bufB, bufA);
    gemm_tc_kernel<<<NUM_NODES / 128, 256, gemm_smem>>>(bufA, whi + 16384, wlo + 16384, b1, bufB);
    // layer 2
    agg_mma_kernel<<<agg_grid, 256, agg_smem>>>(bufB, bufA);
    gemm_tc_kernel<<<NUM_NODES / 128, 256, gemm_smem>>>(bufA, whi + 32768, wlo + 32768, b2, bufB);

    key_kernel<<<NUM_NODES / 8, 256>>>();
    topk_kernel<<<BGRAPH / 8, 256>>>();
    sort_rows_kernel<<<BGRAPH * KTOP, 128>>>();
    head_kernel<<<BGRAPH, 128>>>(conv1_w, conv1_b, conv2_w, conv2_b, out);
}

// round 7
// speedup vs baseline: 1.4343x; 1.0125x over previous
#include <cuda_runtime.h>
#include <cuda_bf16.h>
#include <math.h>
#include <stdint.h>

// Problem constants
#define BGRAPH 256
#define NNODE  256
#define DFEAT  128
#define KTOP   10
#define E_PER  8192
#define NUM_NODES (BGRAPH * NNODE)     // 65536
#define E_TOT (BGRAPH * E_PER)         // 2097152
#define OUT_CH 128
#define HALF_D 64
#define FULLMASK 0xffffffffu

// ---------------- scratch (device globals; no runtime allocation) -------------
__device__ float g_bufA[NUM_NODES * DFEAT];
__device__ float g_bufB[NUM_NODES * DFEAT];
__device__ float g_od[NUM_NODES];
__device__ float g_id[NUM_NODES];
__device__ __nv_bfloat16 g_adj[(size_t)BGRAPH * NNODE * NNODE];  // 32 MB dense adjacency
__device__ float g_key[NUM_NODES];
__device__ int   g_topk[BGRAPH * KTOP];
__device__ float g_pooled[BGRAPH * KTOP * DFEAT];
__device__ float g_Whi[3 * DFEAT * DFEAT];
__device__ float g_Wlo[3 * DFEAT * DFEAT];

__device__ __forceinline__ uint32_t smem_u32(const void* p) {
    uint32_t a;
    asm("{ .reg .u64 t; cvta.to.shared.u64 t, %1; cvt.u32.u64 %0, t; }" : "=r"(a) : "l"(p));
    return a;
}
__device__ __forceinline__ void ldmatrix_x4(unsigned& r0, unsigned& r1, unsigned& r2,
                                            unsigned& r3, uint32_t addr) {
    asm volatile("ldmatrix.sync.aligned.m8n8.x4.shared.b16 {%0,%1,%2,%3}, [%4];"
                 : "=r"(r0), "=r"(r1), "=r"(r2), "=r"(r3) : "r"(addr));
}

// =============================================================================
// kernel 1: graph build — zero dense Adj (uint4), edge-count bf16 atomics
// (exact small ints -> order-independent -> deterministic), degree isqrt.
// =============================================================================
__global__ void build_kernel(const int* __restrict__ src, const int* __restrict__ dst) {
    int b = blockIdx.x;
    int tid = threadIdx.x;
    __shared__ int sdin[256], sdout[256];
    __nv_bfloat16* adjb = g_adj + (size_t)b * (NNODE * NNODE);

    uint4 z4 = make_uint4(0, 0, 0, 0);
    uint4* az = (uint4*)adjb;
    #pragma unroll 8
    for (int i = tid; i < NNODE * NNODE / 8; i += 256) az[i] = z4;
    sdin[tid] = 0; sdout[tid] = 0;
    __syncthreads();

    int ebase = b * E_PER;
    const __nv_bfloat16 one = __float2bfloat16(1.0f);
    for (int e = tid; e < E_PER; e += 256) {
        int s = src[ebase + e] & 255;
        int d = dst[ebase + e] & 255;
        atomicAdd(&sdout[s], 1);
        atomicAdd(&sdin[d], 1);
        atomicAdd(adjb + d * NNODE + s, one);
    }
    __syncthreads();

    int gn = b * NNODE + tid;
    g_od[gn] = 1.0f / sqrtf((float)max(sdout[tid], 1));
    g_id[gn] = 1.0f / sqrtf((float)max(sdin[tid], 1));
}

// =============================================================================
// kernel 2: dense-adjacency aggregation via bf16 mma.sync + ldmatrix.
// out[gbase+m, half*64+n] = id[m] * sum_s Adj[m][s] * od[s] * h[s][half*64+n]
// Block = (graph, half): M=256, N=64, K=256 (chunks of 64). 2-pass hi/lo on h.
// =============================================================================
#define MMA_BF16(d, a, b0v, b1v)                                                 \
    asm volatile("mma.sync.aligned.m16n8k16.row.col.f32.bf16.bf16.f32 "          \
                 "{%0,%1,%2,%3}, {%4,%5,%6,%7}, {%8,%9}, {%0,%1,%2,%3};\n"       \
                 : "+f"(d[0]), "+f"(d[1]), "+f"(d[2]), "+f"(d[3])                \
                 : "r"(a[0]), "r"(a[1]), "r"(a[2]), "r"(a[3]), "r"(b0v), "r"(b1v))

#define KPAD 72   // bf16 row stride: 144B -> 16B shift per row -> conflict-free

__global__ void __launch_bounds__(256, 2) agg_mma_kernel(
    const float* __restrict__ h_in, float* __restrict__ out)
{
    extern __shared__ __nv_bfloat16 sm[];
    __nv_bfloat16* sA  = sm;                 // [256][KPAD]  Adj chunk (rows=dst, cols=src)
    __nv_bfloat16* sBh = sm + 256 * KPAD;    // [64][KPAD]   feat-major (n-major) h hi
    __nv_bfloat16* sBl = sBh + 64 * KPAD;    // [64][KPAD]   h lo

    int b = blockIdx.x, half = blockIdx.y;
    int tid = threadIdx.x;
    int lane = tid & 31, warp = tid >> 5;
    int wm = warp >> 1, wn = warp & 1;       // warp tile 64(M) x 32(N)
    int g = lane >> 2, t = lane & 3;
    int gbase = b * NNODE;
    const __nv_bfloat16* adjb = g_adj + (size_t)b * (NNODE * NNODE);

    // ldmatrix per-lane addressing: lanes 0-15 -> 16 rows @ k, lanes 16-31 -> same rows @ k+8
    int lrow = lane & 15, lkh = lane >> 4;
    uint32_t sA_u  = smem_u32(sA);
    uint32_t sBh_u = smem_u32(sBh);
    uint32_t sBl_u = smem_u32(sBl);
    uint32_t aaddr[4], bhaddr[2], bladdr[2];
    #pragma unroll
    for (int mt = 0; mt < 4; mt++)
        aaddr[mt] = sA_u + 2u * ((wm * 64 + mt * 16 + lrow) * KPAD + lkh * 8);
    #pragma unroll
    for (int j = 0; j < 2; j++) {
        bhaddr[j] = sBh_u + 2u * ((wn * 32 + j * 16 + lrow) * KPAD + lkh * 8);
        bladdr[j] = sBl_u + 2u * ((wn * 32 + j * 16 + lrow) * KPAD + lkh * 8);
    }

    float acc[4][4][4];
    #pragma unroll
    for (int mt = 0; mt < 4; mt++)
        #pragma unroll
        for (int nt = 0; nt < 4; nt++)
            #pragma unroll
            for (int q = 0; q < 4; q++) acc[mt][nt][q] = 0.f;

    for (int kc = 0; kc < 4; kc++) {
        int k0 = kc * 64;
        __syncthreads();
        // Adj chunk: 256 rows x 64 bf16 (128B per row = 8 uint4)
        #pragma unroll
        for (int i = tid; i < 2048; i += 256) {
            int r = i >> 3, q = i & 7;
            const uint4* s4 = (const uint4*)(adjb + r * NNODE + k0);
            *(uint4*)(sA + r * KPAD + q * 8) = s4[q];
        }
        // h chunk: 64 src-nodes x 64 feats, scale by od, split hi/lo, store n-major
        #pragma unroll
        for (int i = tid; i < 1024; i += 256) {
            int kk = i >> 4, f4 = i & 15;
            float od = __ldg(&g_od[gbase + k0 + kk]);
            float4 v = *(const float4*)&h_in[(size_t)(gbase + k0 + kk) * DFEAT + half * HALF_D + f4 * 4];
            float xs[4] = {v.x * od, v.y * od, v.z * od, v.w * od};
            #pragma unroll
            for (int e = 0; e < 4; e++) {
                __nv_bfloat16 hi = __float2bfloat16(xs[e]);
                __nv_bfloat16 lo = __float2bfloat16(xs[e] - __bfloat162float(hi));
                sBh[(f4 * 4 + e) * KPAD + kk] = hi;
                sBl[(f4 * 4 + e) * KPAD + kk] = lo;
            }
        }
        __syncthreads();

        #pragma unroll
        for (int ks = 0; ks < 4; ks++) {
            uint32_t kb = 2u * (ks * 16);
            unsigned a[4][4];
            #pragma unroll
            for (int mt = 0; mt < 4; mt++)
                ldmatrix_x4(a[mt][0], a[mt][1], a[mt][2], a[mt][3], aaddr[mt] + kb);
            unsigned bh[2][4], bl[2][4];
            #pragma unroll
            for (int j = 0; j < 2; j++) {
                ldmatrix_x4(bh[j][0], bh[j][1], bh[j][2], bh[j][3], bhaddr[j] + kb);
                ldmatrix_x4(bl[j][0], bl[j][1], bl[j][2], bl[j][3], bladdr[j] + kb);
            }
            #pragma unroll
            for (int j = 0; j < 2; j++) {
                #pragma unroll
                for (int mt = 0; mt < 4; mt++) {
                    MMA_BF16(acc[mt][2 * j],     a[mt], bh[j][0], bh[j][2]);
                    MMA_BF16(acc[mt][2 * j + 1], a[mt], bh[j][1], bh[j][3]);
                    MMA_BF16(acc[mt][2 * j],     a[mt], bl[j][0], bl[j][2]);
                    MMA_BF16(acc[mt][2 * j + 1], a[mt], bl[j][1], bl[j][3]);
                }
            }
        }
    }

    // epilogue: scale by id[dst], store
    #pragma unroll
    for (int mt = 0; mt < 4; mt++) {
        int m = wm * 64 + mt * 16 + g;
        float id0 = g_id[gbase + m];
        float id1 = g_id[gbase + m + 8];
        #pragma unroll
        for (int nt = 0; nt < 4; nt++) {
            int n = half * HALF_D + wn * 32 + nt * 8 + 2 * t;
            float2 o0, o1;
            o0.x = acc[mt][nt][0] * id0; o0.y = acc[mt][nt][1] * id0;
            o1.x = acc[mt][nt][2] * id1; o1.y = acc[mt][nt][3] * id1;
            *(float2*)&out[(size_t)(gbase + m) * DFEAT + n] = o0;
            *(float2*)&out[(size_t)(gbase + m + 8) * DFEAT + n] = o1;
        }
    }
}

// =============================================================================
// kernel 3: per-layer W hi/lo tf32 split (one launch for all 3 layers)
// =============================================================================
__device__ __forceinline__ unsigned f2tf32(float x) {
    unsigned r;
    asm("cvt.rna.tf32.f32 %0, %1;" : "=r"(r) : "f"(x));
    return r;
}

__global__ void wsplit_kernel(const float* __restrict__ W0, const float* __restrict__ W1,
                              const float* __restrict__ W2) {
    int layer = blockIdx.x >> 6;
    int i = (blockIdx.x & 63) * 256 + threadIdx.x;
    const float* W = (layer == 0) ? W0 : ((layer == 1) ? W1 : W2);
    float x = W[i];
    unsigned hb = f2tf32(x);
    float hf = __uint_as_float(hb);
    g_Whi[layer * 16384 + i] = hf;
    g_Wlo[layer * 16384 + i] = __uint_as_float(f2tf32(x - hf));
}

// =============================================================================
// kernel 4: tf32 tensor-core GEMM + bias + relu  (3xTF32 split ~ fp32 accuracy)
// =============================================================================
#define MMA_TF32(d, a, b0, b1)                                                  \
    asm volatile("mma.sync.aligned.m16n8k8.row.col.f32.tf32.tf32.f32 "          \
                 "{%0,%1,%2,%3}, {%4,%5,%6,%7}, {%8,%9}, {%0,%1,%2,%3};\n"      \
                 : "+f"(d[0]), "+f"(d[1]), "+f"(d[2]), "+f"(d[3])               \
                 : "r"(a[0]), "r"(a[1]), "r"(a[2]), "r"(a[3]), "r"(b0), "r"(b1))

#define SROW 136   // padded smem row (floats) -> conflict-free fragment loads

__global__ void __launch_bounds__(256, 2) gemm_tc_kernel(
    const float* __restrict__ A,
    const float* __restrict__ whi, const float* __restrict__ wlo,
    const float* __restrict__ bias, float* __restrict__ C)
{
    extern __shared__ float smem[];
    float* sAh = smem;                 // [32][SROW] layout [k][m]
    float* sAl = sAh + 32 * SROW;
    float* sBh = sAl + 32 * SROW;     // [32][SROW] layout [k][n]
    float* sBl = sBh + 32 * SROW;
    __shared__ float sbias[128];

    int tid = threadIdx.x;
    int lane = tid & 31, warp = tid >> 5;
    int wm = warp >> 1, wn = warp & 1;   // warp tile: 32 (M) x 64 (N)
    int gid = lane >> 2, tig = lane & 3;
    int m0 = blockIdx.x * 128;

    if (tid < 128) sbias[tid] = bias[tid];

    float acc[2][8][4];
    #pragma unroll
    for (int mt = 0; mt < 2; mt++)
        #pragma unroll
        for (int nt = 0; nt < 8; nt++)
            #pragma unroll
            for (int q = 0; q < 4; q++) acc[mt][nt][q] = 0.f;

    int lm = tid >> 1;        // A row within tile  (0..127)
    int lh = tid & 1;         // A col half (16 cols each)
    int bk = tid >> 3;        // W row within chunk (0..31)
    int bg = tid & 7;         // W col group of 16

    for (int k0 = 0; k0 < 128; k0 += 32) {
        __syncthreads();
        // load+convert A chunk: 128 x 32, store transposed [k][m]
        const float* Ap = A + (size_t)(m0 + lm) * 128 + k0 + lh * 16;
        #pragma unroll
        for (int q = 0; q < 4; q++) {
            float4 v = *(const float4*)(Ap + q * 4);
            int kb = lh * 16 + q * 4;
            float xs[4] = {v.x, v.y, v.z, v.w};
            #pragma unroll
            for (int e = 0; e < 4; e++) {
                unsigned hb = f2tf32(xs[e]);
                float hf = __uint_as_float(hb);
                unsigned lb = f2tf32(xs[e] - hf);
                sAh[(kb + e) * SROW + lm] = hf;
                sAl[(kb + e) * SROW + lm] = __uint_as_float(lb);
            }
        }
        // W chunk: pre-split, plain float4 copies
        #pragma unroll
        for (int q = 0; q < 4; q++) {
            *(float4*)&sBh[bk * SROW + bg * 16 + q * 4] =
                *(const float4*)&whi[(k0 + bk) * 128 + bg * 16 + q * 4];
            *(float4*)&sBl[bk * SROW + bg * 16 + q * 4] =
                *(const float4*)&wlo[(k0 + bk) * 128 + bg * 16 + q * 4];
        }
        __syncthreads();

        #pragma unroll
        for (int kk = 0; kk < 32; kk += 8) {
            unsigned ah[2][4], al[2][4];
            #pragma unroll
            for (int mt = 0; mt < 2; mt++) {
                int m = wm * 32 + mt * 16 + gid;
                int r0 = (kk + tig) * SROW + m;
                int r4 = (kk + tig + 4) * SROW + m;
                ah[mt][0] = __float_as_uint(sAh[r0]);
                ah[mt][1] = __float_as_uint(sAh[r0 + 8]);
                ah[mt][2] = __float_as_uint(sAh[r4]);
                ah[mt][3] = __float_as_uint(sAh[r4 + 8]);
                al[mt][0] = __float_as_uint(sAl[r0]);
                al[mt][1] = __float_as_uint(sAl[r0 + 8]);
                al[mt][2] = __float_as_uint(sAl[r4]);
                al[mt][3] = __float_as_uint(sAl[r4 + 8]);
            }
            #pragma unroll
            for (int nt = 0; nt < 8; nt++) {
                int n = wn * 64 + nt * 8 + gid;
                int c0 = (kk + tig) * SROW + n;
                int c4 = (kk + tig + 4) * SROW + n;
                unsigned bh0 = __float_as_uint(sBh[c0]);
                unsigned bh1 = __float_as_uint(sBh[c4]);
                unsigned bl0 = __float_as_uint(sBl[c0]);
                unsigned bl1 = __float_as_uint(sBl[c4]);
                MMA_TF32(acc[0][nt], ah[0], bh0, bh1);
                MMA_TF32(acc[1][nt], ah[1], bh0, bh1);
                MMA_TF32(acc[0][nt], al[0], bh0, bh1);
                MMA_TF32(acc[1][nt], al[1], bh0, bh1);
                MMA_TF32(acc[0][nt], ah[0], bl0, bl1);
                MMA_TF32(acc[1][nt], ah[1], bl0, bl1);
            }
        }
    }

    // epilogue: bias + relu, coalesced float2 stores
    #pragma unroll
    for (int mt = 0; mt < 2; mt++) {
        int r = m0 + wm * 32 + mt * 16 + gid;
        #pragma unroll
        for (int nt = 0; nt < 8; nt++) {
            int c = wn * 64 + nt * 8 + 2 * tig;
            float b0v = sbias[c], b1v = sbias[c + 1];
            float2 o0, o1;
            o0.x = fmaxf(acc[mt][nt][0] + b0v, 0.f);
            o0.y = fmaxf(acc[mt][nt][1] + b1v, 0.f);
            o1.x = fmaxf(acc[mt][nt][2] + b0v, 0.f);
            o1.y = fmaxf(acc[mt][nt][3] + b1v, 0.f);
            *(float2*)&C[(size_t)r * 128 + c] = o0;
            *(float2*)&C[(size_t)(r + 8) * 128 + c] = o1;
        }
    }
}

// ---------------- kernel 5: per-node row max (the sort key) ------------------
__global__ void key_kernel() {
    int gn = blockIdx.x * 8 + (threadIdx.x >> 5);
    int lane = threadIdx.x & 31;
    float4 v = *(const float4*)&g_bufB[(size_t)gn * DFEAT + lane * 4];
    float m = fmaxf(fmaxf(v.x, v.y), fmaxf(v.z, v.w));
    #pragma unroll
    for (int off = 16; off; off >>= 1)
        m = fmaxf(m, __shfl_xor_sync(FULLMASK, m, off));
    if (lane == 0) g_key[gn] = m;
}

// ---------------- kernel 6: top-k per graph (exact lax.top_k semantics) ------
__global__ void topk_kernel() {
    int w = threadIdx.x >> 5, lane = threadIdx.x & 31;
    int b = blockIdx.x * 8 + w;
    float v[8];
    #pragma unroll
    for (int r = 0; r < 8; r++) v[r] = g_key[b * NNODE + r * 32 + lane];
    for (int t = 0; t < KTOP; t++) {
        float bv = -INFINITY;
        int bi = 0;
        #pragma unroll
        for (int r = 0; r < 8; r++) {
            int idx = r * 32 + lane;
            if (v[r] > bv || (v[r] == bv && idx < bi)) { bv = v[r]; bi = idx; }
        }
        #pragma unroll
        for (int off = 16; off; off >>= 1) {
            float ov = __shfl_xor_sync(FULLMASK, bv, off);
            int   oi = __shfl_xor_sync(FULLMASK, bi, off);
            if (ov > bv || (ov == bv && oi < bi)) { bv = ov; bi = oi; }
        }
        if (lane == 0) g_topk[b * KTOP + t] = bi;
        if (lane == (bi & 31)) v[bi >> 5] = -INFINITY;
    }
}

// ---------------- kernel 7: sort the 2560 selected rows (ascending) ----------
__global__ void sort_rows_kernel() {
    int i = blockIdx.x;          // 0..2559
    int tid = threadIdx.x;       // 128
    __shared__ float s[128];
    int b = i / KTOP;
    int node = g_topk[i];
    s[tid] = g_bufB[(size_t)(b * NNODE + node) * DFEAT + tid];
    __syncthreads();
    for (int k = 2; k <= 128; k <<= 1) {
        for (int j = k >> 1; j > 0; j >>= 1) {
            int p = tid ^ j;
            if (p > tid) {
                bool up = ((tid & k) == 0);
                float a = s[tid], c = s[p];
                if ((a > c) == up) { s[tid] = c; s[p] = a; }
            }
            __syncthreads();
        }
    }
    g_pooled[i * DFEAT + tid] = s[tid];
}

// ---------------- kernel 8: conv1 + maxpool + conv2 head ---------------------
__global__ void head_kernel(const float* __restrict__ w1, const float* __restrict__ b1c,
                            const float* __restrict__ w2, const float* __restrict__ b2c,
                            float* __restrict__ out)
{
    int b = blockIdx.x;
    int tid = threadIdx.x; // 128
    __shared__ float sp[KTOP][132];
    __shared__ float sw1[64][132];
    __shared__ float sc1[64][KTOP];
    __shared__ float sc1p[64][5];

    for (int i = tid; i < KTOP * DFEAT; i += 128)
        sp[i / DFEAT][i % DFEAT] = g_pooled[b * KTOP * DFEAT + i];
    for (int i = tid; i < 64 * DFEAT; i += 128)
        sw1[i / DFEAT][i % DFEAT] = w1[i];
    __syncthreads();

    for (int o = tid; o < 64 * KTOP; o += 128) {
        int oc = o / KTOP, k = o % KTOP;
        float acc = b1c[oc];
        #pragma unroll 8
        for (int d = 0; d < DFEAT; d++) acc += sp[k][d] * sw1[oc][d];
        sc1[oc][k] = fmaxf(acc, 0.f);
    }
    __syncthreads();
    for (int o = tid; o < 64 * 5; o += 128) {
        int ic = o / 5, t = o % 5;
        sc1p[ic][t] = fmaxf(sc1[ic][2 * t], sc1[ic][2 * t + 1]);
    }
    __syncthreads();
    float acc = b2c[tid];
    const float* wrow = w2 + tid * 320;
    const float* cp = &sc1p[0][0];
    #pragma unroll 8
    for (int q = 0; q < 320; q++) acc += cp[q] * wrow[q];
    out[b * OUT_CH + tid] = fmaxf(acc, 0.f);
}

// ---------------- launcher ---------------------------------------------------
extern "C" void kernel_launch(void* const* d_in, const int* in_sizes, int n_in,
                              void* d_out, int out_size)
{
    const float* feats   = (const float*)d_in[0];
    const int*   src     = (const int*)d_in[1];
    const int*   dst     = (const int*)d_in[2];
    const float* W0      = (const float*)d_in[3];
    const float* b0      = (const float*)d_in[4];
    const float* W1      = (const float*)d_in[5];
    const float* b1      = (const float*)d_in[6];
    const float* W2      = (const float*)d_in[7];
    const float* b2      = (const float*)d_in[8];
    const float* conv1_w = (const float*)d_in[9];
    const float* conv1_b = (const float*)d_in[10];
    const float* conv2_w = (const float*)d_in[11];
    const float* conv2_b = (const float*)d_in[12];
    float* out = (float*)d_out;

    int agg_smem  = (256 * KPAD + 2 * 64 * KPAD) * (int)sizeof(__nv_bfloat16);  // 55296
    int gemm_smem = 4 * 32 * SROW * 4;
    cudaFuncSetAttribute(agg_mma_kernel, cudaFuncAttributeMaxDynamicSharedMemorySize, agg_smem);
    cudaFuncSetAttribute(gemm_tc_kernel, cudaFuncAttributeMaxDynamicSharedMemorySize, gemm_smem);

    float* bufA;  cudaGetSymbolAddress((void**)&bufA, g_bufA);
    float* bufB;  cudaGetSymbolAddress((void**)&bufB, g_bufB);
    float* whi;   cudaGetSymbolAddress((void**)&whi, g_Whi);
    float* wlo;   cudaGetSymbolAddress((void**)&wlo, g_Wlo);

    build_kernel<<<BGRAPH, 256>>>(src, dst);
    wsplit_kernel<<<192, 256>>>(W0, W1, W2);

    dim3 agg_grid(BGRAPH, 2);
    // layer 0
    agg_mma_kernel<<<agg_grid, 256, agg_smem>>>(feats, bufA);
    gemm_tc_kernel<<<NUM_NODES / 128, 256, gemm_smem>>>(bufA, whi, wlo, b0, bufB);
    // layer 1
    agg_mma_kernel<<<agg_grid, 256, agg_smem>>>(bufB, bufA);
    gemm_tc_kernel<<<NUM_NODES / 128, 256, gemm_smem>>>(bufA, whi + 16384, wlo + 16384, b1, bufB);
    // layer 2
    agg_mma_kernel<<<agg_grid, 256, agg_smem>>>(bufB, bufA);
    gemm_tc_kernel<<<NUM_NODES / 128, 256, gemm_smem>>>(bufA, whi + 32768, wlo + 32768, b2, bufB);

    key_kernel<<<NUM_NODES / 8, 256>>>();
    topk_kernel<<<BGRAPH / 8, 256>>>();
    sort_rows_kernel<<<BGRAPH * KTOP, 128>>>();
    head_kernel<<<BGRAPH, 128>>>(conv1_w, conv1_b, conv2_w, conv2_b, out);
}

// round 9
// speedup vs baseline: 1.7998x; 1.2548x over previous
#include <cuda_runtime.h>
#include <cuda_bf16.h>
#include <math.h>
#include <stdint.h>

// Problem constants
#define BGRAPH 256
#define NNODE  256
#define DFEAT  128
#define KTOP   10
#define E_PER  8192
#define NUM_NODES (BGRAPH * NNODE)     // 65536
#define E_TOT (BGRAPH * E_PER)         // 2097152
#define OUT_CH 128
#define HALF_D 64
#define FULLMASK 0xffffffffu

// ---------------- scratch (device globals; no runtime allocation) -------------
__device__ float g_bufA[NUM_NODES * DFEAT];
__device__ float g_bufB[NUM_NODES * DFEAT];
__device__ float g_od[NUM_NODES];
__device__ float g_id[NUM_NODES];
__device__ __nv_bfloat16 g_adj[(size_t)BGRAPH * NNODE * NNODE];  // 32 MB dense adjacency
__device__ float g_key[NUM_NODES];
__device__ int   g_topk[BGRAPH * KTOP];
__device__ float g_pooled[BGRAPH * KTOP * DFEAT];
__device__ __nv_bfloat16 g_Wthi[3 * DFEAT * DFEAT];   // W transposed [n][k], bf16 hi
__device__ __nv_bfloat16 g_Wtlo[3 * DFEAT * DFEAT];   // W transposed [n][k], bf16 lo

__device__ __forceinline__ uint32_t smem_u32(const void* p) {
    uint32_t a;
    asm("{ .reg .u64 t; cvta.to.shared.u64 t, %1; cvt.u32.u64 %0, t; }" : "=r"(a) : "l"(p));
    return a;
}
__device__ __forceinline__ void ldmatrix_x4(unsigned& r0, unsigned& r1, unsigned& r2,
                                            unsigned& r3, uint32_t addr) {
    asm volatile("ldmatrix.sync.aligned.m8n8.x4.shared.b16 {%0,%1,%2,%3}, [%4];"
                 : "=r"(r0), "=r"(r1), "=r"(r2), "=r"(r3) : "r"(addr));
}
__device__ __forceinline__ unsigned pack_bf16(__nv_bfloat16 a, __nv_bfloat16 b) {
    return ((unsigned)__bfloat16_as_ushort(b) << 16) | __bfloat16_as_ushort(a);
}

#define MMA_BF16(d, a, b0v, b1v)                                                 \
    asm volatile("mma.sync.aligned.m16n8k16.row.col.f32.bf16.bf16.f32 "          \
                 "{%0,%1,%2,%3}, {%4,%5,%6,%7}, {%8,%9}, {%0,%1,%2,%3};\n"       \
                 : "+f"(d[0]), "+f"(d[1]), "+f"(d[2]), "+f"(d[3])                \
                 : "r"(a[0]), "r"(a[1]), "r"(a[2]), "r"(a[3]), "r"(b0v), "r"(b1v))

#define KPAD 72   // bf16 row stride: 144B -> 16B shift per row -> conflict-free

// =============================================================================
// kernel 1: graph build — zero dense Adj (uint4), edge-count bf16 atomics
// (exact small ints -> order-independent -> deterministic), degree isqrt.
// =============================================================================
__global__ void build_kernel(const int* __restrict__ src, const int* __restrict__ dst) {
    int b = blockIdx.x;
    int tid = threadIdx.x;
    __shared__ int sdin[256], sdout[256];
    __nv_bfloat16* adjb = g_adj + (size_t)b * (NNODE * NNODE);

    uint4 z4 = make_uint4(0, 0, 0, 0);
    uint4* az = (uint4*)adjb;
    #pragma unroll 8
    for (int i = tid; i < NNODE * NNODE / 8; i += 256) az[i] = z4;
    sdin[tid] = 0; sdout[tid] = 0;
    __syncthreads();

    int ebase = b * E_PER;
    const __nv_bfloat16 one = __float2bfloat16(1.0f);
    for (int e = tid; e < E_PER; e += 256) {
        int s = src[ebase + e] & 255;
        int d = dst[ebase + e] & 255;
        atomicAdd(&sdout[s], 1);
        atomicAdd(&sdin[d], 1);
        atomicAdd(adjb + d * NNODE + s, one);
    }
    __syncthreads();

    int gn = b * NNODE + tid;
    g_od[gn] = 1.0f / sqrtf((float)max(sdout[tid], 1));
    g_id[gn] = 1.0f / sqrtf((float)max(sdin[tid], 1));
}

// =============================================================================
// kernel 2: dense-adjacency aggregation via bf16 mma.sync + ldmatrix.
// out[gbase+m, half*64+n] = id[m] * sum_s Adj[m][s] * od[s] * h[s][half*64+n]
// Block = (graph, half): M=256, N=64, K=256 (chunks of 64). 2-pass hi/lo on h.
// =============================================================================
__global__ void __launch_bounds__(256, 2) agg_mma_kernel(
    const float* __restrict__ h_in, float* __restrict__ out)
{
    extern __shared__ __nv_bfloat16 sm[];
    __nv_bfloat16* sA  = sm;                 // [256][KPAD]  Adj chunk (rows=dst, cols=src)
    __nv_bfloat16* sBh = sm + 256 * KPAD;    // [64][KPAD]   feat-major (n-major) h hi
    __nv_bfloat16* sBl = sBh + 64 * KPAD;    // [64][KPAD]   h lo

    int b = blockIdx.x, half = blockIdx.y;
    int tid = threadIdx.x;
    int lane = tid & 31, warp = tid >> 5;
    int wm = warp >> 1, wn = warp & 1;       // warp tile 64(M) x 32(N)
    int g = lane >> 2, t = lane & 3;
    int gbase = b * NNODE;
    const __nv_bfloat16* adjb = g_adj + (size_t)b * (NNODE * NNODE);

    int lrow = lane & 15, lkh = lane >> 4;
    uint32_t sA_u  = smem_u32(sA);
    uint32_t sBh_u = smem_u32(sBh);
    uint32_t sBl_u = smem_u32(sBl);
    uint32_t aaddr[4], bhaddr[2], bladdr[2];
    #pragma unroll
    for (int mt = 0; mt < 4; mt++)
        aaddr[mt] = sA_u + 2u * ((wm * 64 + mt * 16 + lrow) * KPAD + lkh * 8);
    #pragma unroll
    for (int j = 0; j < 2; j++) {
        bhaddr[j] = sBh_u + 2u * ((wn * 32 + j * 16 + lrow) * KPAD + lkh * 8);
        bladdr[j] = sBl_u + 2u * ((wn * 32 + j * 16 + lrow) * KPAD + lkh * 8);
    }

    float acc[4][4][4];
    #pragma unroll
    for (int mt = 0; mt < 4; mt++)
        #pragma unroll
        for (int nt = 0; nt < 4; nt++)
            #pragma unroll
            for (int q = 0; q < 4; q++) acc[mt][nt][q] = 0.f;

    for (int kc = 0; kc < 4; kc++) {
        int k0 = kc * 64;
        __syncthreads();
        #pragma unroll
        for (int i = tid; i < 2048; i += 256) {
            int r = i >> 3, q = i & 7;
            const uint4* s4 = (const uint4*)(adjb + r * NNODE + k0);
            *(uint4*)(sA + r * KPAD + q * 8) = s4[q];
        }
        #pragma unroll
        for (int i = tid; i < 1024; i += 256) {
            int kk = i >> 4, f4 = i & 15;
            float od = __ldg(&g_od[gbase + k0 + kk]);
            float4 v = *(const float4*)&h_in[(size_t)(gbase + k0 + kk) * DFEAT + half * HALF_D + f4 * 4];
            float xs[4] = {v.x * od, v.y * od, v.z * od, v.w * od};
            #pragma unroll
            for (int e = 0; e < 4; e++) {
                __nv_bfloat16 hi = __float2bfloat16(xs[e]);
                __nv_bfloat16 lo = __float2bfloat16(xs[e] - __bfloat162float(hi));
                sBh[(f4 * 4 + e) * KPAD + kk] = hi;
                sBl[(f4 * 4 + e) * KPAD + kk] = lo;
            }
        }
        __syncthreads();

        #pragma unroll
        for (int ks = 0; ks < 4; ks++) {
            uint32_t kb = 2u * (ks * 16);
            unsigned a[4][4];
            #pragma unroll
            for (int mt = 0; mt < 4; mt++)
                ldmatrix_x4(a[mt][0], a[mt][1], a[mt][2], a[mt][3], aaddr[mt] + kb);
            unsigned bh[2][4], bl[2][4];
            #pragma unroll
            for (int j = 0; j < 2; j++) {
                ldmatrix_x4(bh[j][0], bh[j][1], bh[j][2], bh[j][3], bhaddr[j] + kb);
                ldmatrix_x4(bl[j][0], bl[j][1], bl[j][2], bl[j][3], bladdr[j] + kb);
            }
            #pragma unroll
            for (int j = 0; j < 2; j++) {
                #pragma unroll
                for (int mt = 0; mt < 4; mt++) {
                    MMA_BF16(acc[mt][2 * j],     a[mt], bh[j][0], bh[j][2]);
                    MMA_BF16(acc[mt][2 * j + 1], a[mt], bh[j][1], bh[j][3]);
                    MMA_BF16(acc[mt][2 * j],     a[mt], bl[j][0], bl[j][2]);
                    MMA_BF16(acc[mt][2 * j + 1], a[mt], bl[j][1], bl[j][3]);
                }
            }
        }
    }

    #pragma unroll
    for (int mt = 0; mt < 4; mt++) {
        int m = wm * 64 + mt * 16 + g;
        float id0 = g_id[gbase + m];
        float id1 = g_id[gbase + m + 8];
        #pragma unroll
        for (int nt = 0; nt < 4; nt++) {
            int n = half * HALF_D + wn * 32 + nt * 8 + 2 * t;
            float2 o0, o1;
            o0.x = acc[mt][nt][0] * id0; o0.y = acc[mt][nt][1] * id0;
            o1.x = acc[mt][nt][2] * id1; o1.y = acc[mt][nt][3] * id1;
            *(float2*)&out[(size_t)(gbase + m) * DFEAT + n] = o0;
            *(float2*)&out[(size_t)(gbase + m + 8) * DFEAT + n] = o1;
        }
    }
}

// =============================================================================
// kernel 3: W -> W^T bf16 hi/lo split (one launch, all 3 layers)
// =============================================================================
__global__ void wsplit_kernel(const float* __restrict__ W0, const float* __restrict__ W1,
                              const float* __restrict__ W2) {
    int layer = blockIdx.x >> 6;
    int i = (blockIdx.x & 63) * 256 + threadIdx.x;   // i = k*128 + n
    const float* W = (layer == 0) ? W0 : ((layer == 1) ? W1 : W2);
    float x = W[i];
    int k = i >> 7, n = i & 127;
    __nv_bfloat16 hi = __float2bfloat16(x);
    __nv_bfloat16 lo = __float2bfloat16(x - __bfloat162float(hi));
    g_Wthi[layer * 16384 + n * 128 + k] = hi;
    g_Wtlo[layer * 16384 + n * 128 + k] = lo;
}

// =============================================================================
// kernel 4: bf16 3-pass tensor-core GEMM + bias + relu (ldmatrix everywhere)
// C[M,128] = relu(A[M,128] @ W[128,128] + bias), W^T pre-split bf16.
// Block tile 128(M) x 128(N), K chunks of 64. Warp tile 32(M) x 64(N).
// =============================================================================
__global__ void __launch_bounds__(256, 2) gemm_bf16_kernel(
    const float* __restrict__ A,
    const __nv_bfloat16* __restrict__ wthi, const __nv_bfloat16* __restrict__ wtlo,
    const float* __restrict__ bias, float* __restrict__ C)
{
    extern __shared__ __nv_bfloat16 sm[];
    __nv_bfloat16* sAh = sm;                  // [128][KPAD]  A hi (m-major)
    __nv_bfloat16* sAl = sAh + 128 * KPAD;    // [128][KPAD]  A lo
    __nv_bfloat16* sBh = sAl + 128 * KPAD;    // [128][KPAD]  W^T hi (n-major)
    __nv_bfloat16* sBl = sBh + 128 * KPAD;    // [128][KPAD]  W^T lo
    __shared__ float sbias[128];

    int tid = threadIdx.x;
    int lane = tid & 31, warp = tid >> 5;
    int wm = warp >> 1, wn = warp & 1;        // warp tile 32(M) x 64(N)
    int g = lane >> 2, t = lane & 3;
    int m0 = blockIdx.x * 128;

    if (tid < 128) sbias[tid] = bias[tid];

    int lrow = lane & 15, lkh = lane >> 4;
    uint32_t sAh_u = smem_u32(sAh), sAl_u = smem_u32(sAl);
    uint32_t sBh_u = smem_u32(sBh), sBl_u = smem_u32(sBl);
    uint32_t ahaddr[2], aladdr[2], bhaddr[4], bladdr[4];
    #pragma unroll
    for (int mt = 0; mt < 2; mt++) {
        uint32_t off = 2u * ((wm * 32 + mt * 16 + lrow) * KPAD + lkh * 8);
        ahaddr[mt] = sAh_u + off;
        aladdr[mt] = sAl_u + off;
    }
    #pragma unroll
    for (int j = 0; j < 4; j++) {
        uint32_t off = 2u * ((wn * 64 + j * 16 + lrow) * KPAD + lkh * 8);
        bhaddr[j] = sBh_u + off;
        bladdr[j] = sBl_u + off;
    }

    float acc[2][8][4];
    #pragma unroll
    for (int mt = 0; mt < 2; mt++)
        #pragma unroll
        for (int nt = 0; nt < 8; nt++)
            #pragma unroll
            for (int q = 0; q < 4; q++) acc[mt][nt][q] = 0.f;

    for (int kc = 0; kc < 2; kc++) {
        __syncthreads();
        // A chunk: 128 rows x 64 k fp32 -> bf16 hi/lo, m-major
        #pragma unroll
        for (int j = 0; j < 8; j++) {
            int i = tid + j * 256;
            int r = i >> 4, kq = (i & 15) * 4;
            float4 v = *(const float4*)&A[(size_t)(m0 + r) * 128 + kc * 64 + kq];
            float xs[4] = {v.x, v.y, v.z, v.w};
            __nv_bfloat16 h[4], l[4];
            #pragma unroll
            for (int e = 0; e < 4; e++) {
                h[e] = __float2bfloat16(xs[e]);
                l[e] = __float2bfloat16(xs[e] - __bfloat162float(h[e]));
            }
            uint2 hv = make_uint2(pack_bf16(h[0], h[1]), pack_bf16(h[2], h[3]));
            uint2 lv = make_uint2(pack_bf16(l[0], l[1]), pack_bf16(l[2], l[3]));
            *(uint2*)(sAh + r * KPAD + kq) = hv;
            *(uint2*)(sAl + r * KPAD + kq) = lv;
        }
        // B chunk: pre-split W^T, pure uint4 copies (128 rows x 64 k)
        #pragma unroll
        for (int j = 0; j < 4; j++) {
            int i = tid + j * 256;
            int n = i >> 3, q = i & 7;
            *(uint4*)(sBh + n * KPAD + q * 8) = *(const uint4*)(wthi + n * 128 + kc * 64 + q * 8);
            *(uint4*)(sBl + n * KPAD + q * 8) = *(const uint4*)(wtlo + n * 128 + kc * 64 + q * 8);
        }
        __syncthreads();

        #pragma unroll
        for (int ks = 0; ks < 4; ks++) {
            uint32_t kb = 2u * (ks * 16);
            unsigned ah[2][4], al[2][4];
            #pragma unroll
            for (int mt = 0; mt < 2; mt++) {
                ldmatrix_x4(ah[mt][0], ah[mt][1], ah[mt][2], ah[mt][3], ahaddr[mt] + kb);
                ldmatrix_x4(al[mt][0], al[mt][1], al[mt][2], al[mt][3], aladdr[mt] + kb);
            }
            #pragma unroll
            for (int jh = 0; jh < 2; jh++) {
                unsigned bh[2][4], bl[2][4];
                #pragma unroll
                for (int jj = 0; jj < 2; jj++) {
                    int j = jh * 2 + jj;
                    ldmatrix_x4(bh[jj][0], bh[jj][1], bh[jj][2], bh[jj][3], bhaddr[j] + kb);
                    ldmatrix_x4(bl[jj][0], bl[jj][1], bl[jj][2], bl[jj][3], bladdr[j] + kb);
                }
                #pragma unroll
                for (int jj = 0; jj < 2; jj++) {
                    int j = jh * 2 + jj;
                    #pragma unroll
                    for (int mt = 0; mt < 2; mt++) {
                        // 3-pass: ah*bh + ah*bl + al*bh
                        MMA_BF16(acc[mt][2 * j],     ah[mt], bh[jj][0], bh[jj][2]);
                        MMA_BF16(acc[mt][2 * j + 1], ah[mt], bh[jj][1], bh[jj][3]);
                        MMA_BF16(acc[mt][2 * j],     ah[mt], bl[jj][0], bl[jj][2]);
                        MMA_BF16(acc[mt][2 * j + 1], ah[mt], bl[jj][1], bl[jj][3]);
                        MMA_BF16(acc[mt][2 * j],     al[mt], bh[jj][0], bh[jj][2]);
                        MMA_BF16(acc[mt][2 * j + 1], al[mt], bh[jj][1], bh[jj][3]);
                    }
                }
            }
        }
    }

    // epilogue: bias + relu, coalesced float2 stores
    #pragma unroll
    for (int mt = 0; mt < 2; mt++) {
        int m = m0 + wm * 32 + mt * 16 + g;
        #pragma unroll
        for (int nt = 0; nt < 8; nt++) {
            int n = wn * 64 + nt * 8 + 2 * t;
            float b0v = sbias[n], b1v = sbias[n + 1];
            float2 o0, o1;
            o0.x = fmaxf(acc[mt][nt][0] + b0v, 0.f);
            o0.y = fmaxf(acc[mt][nt][1] + b1v, 0.f);
            o1.x = fmaxf(acc[mt][nt][2] + b0v, 0.f);
            o1.y = fmaxf(acc[mt][nt][3] + b1v, 0.f);
            *(float2*)&C[(size_t)m * 128 + n] = o0;
            *(float2*)&C[(size_t)(m + 8) * 128 + n] = o1;
        }
    }
}

// ---------------- kernel 5: per-node row max (the sort key) ------------------
__global__ void key_kernel() {
    int gn = blockIdx.x * 8 + (threadIdx.x >> 5);
    int lane = threadIdx.x & 31;
    float4 v = *(const float4*)&g_bufB[(size_t)gn * DFEAT + lane * 4];
    float m = fmaxf(fmaxf(v.x, v.y), fmaxf(v.z, v.w));
    #pragma unroll
    for (int off = 16; off; off >>= 1)
        m = fmaxf(m, __shfl_xor_sync(FULLMASK, m, off));
    if (lane == 0) g_key[gn] = m;
}

// ---------------- kernel 6: top-k per graph (exact lax.top_k semantics) ------
__global__ void topk_kernel() {
    int w = threadIdx.x >> 5, lane = threadIdx.x & 31;
    int b = blockIdx.x * 8 + w;
    float v[8];
    #pragma unroll
    for (int r = 0; r < 8; r++) v[r] = g_key[b * NNODE + r * 32 + lane];
    for (int t = 0; t < KTOP; t++) {
        float bv = -INFINITY;
        int bi = 0;
        #pragma unroll
        for (int r = 0; r < 8; r++) {
            int idx = r * 32 + lane;
            if (v[r] > bv || (v[r] == bv && idx < bi)) { bv = v[r]; bi = idx; }
        }
        #pragma unroll
        for (int off = 16; off; off >>= 1) {
            float ov = __shfl_xor_sync(FULLMASK, bv, off);
            int   oi = __shfl_xor_sync(FULLMASK, bi, off);
            if (ov > bv || (ov == bv && oi < bi)) { bv = ov; bi = oi; }
        }
        if (lane == 0) g_topk[b * KTOP + t] = bi;
        if (lane == (bi & 31)) v[bi >> 5] = -INFINITY;
    }
}

// ---------------- kernel 7: sort the 2560 selected rows (ascending) ----------
__global__ void sort_rows_kernel() {
    int i = blockIdx.x;          // 0..2559
    int tid = threadIdx.x;       // 128
    __shared__ float s[128];
    int b = i / KTOP;
    int node = g_topk[i];
    s[tid] = g_bufB[(size_t)(b * NNODE + node) * DFEAT + tid];
    __syncthreads();
    for (int k = 2; k <= 128; k <<= 1) {
        for (int j = k >> 1; j > 0; j >>= 1) {
            int p = tid ^ j;
            if (p > tid) {
                bool up = ((tid & k) == 0);
                float a = s[tid], c = s[p];
                if ((a > c) == up) { s[tid] = c; s[p] = a; }
            }
            __syncthreads();
        }
    }
    g_pooled[i * DFEAT + tid] = s[tid];
}

// ---------------- kernel 8: conv1 + maxpool + conv2 head ---------------------
__global__ void head_kernel(const float* __restrict__ w1, const float* __restrict__ b1c,
                            const float* __restrict__ w2, const float* __restrict__ b2c,
                            float* __restrict__ out)
{
    int b = blockIdx.x;
    int tid = threadIdx.x; // 128
    __shared__ float sp[KTOP][132];
    __shared__ float sw1[64][132];
    __shared__ float sc1[64][KTOP];
    __shared__ float sc1p[64][5];

    for (int i = tid; i < KTOP * DFEAT; i += 128)
        sp[i / DFEAT][i % DFEAT] = g_pooled[b * KTOP * DFEAT + i];
    for (int i = tid; i < 64 * DFEAT; i += 128)
        sw1[i / DFEAT][i % DFEAT] = w1[i];
    __syncthreads();

    for (int o = tid; o < 64 * KTOP; o += 128) {
        int oc = o / KTOP, k = o % KTOP;
        float acc = b1c[oc];
        #pragma unroll 8
        for (int d = 0; d < DFEAT; d++) acc += sp[k][d] * sw1[oc][d];
        sc1[oc][k] = fmaxf(acc, 0.f);
    }
    __syncthreads();
    for (int o = tid; o < 64 * 5; o += 128) {
        int ic = o / 5, t = o % 5;
        sc1p[ic][t] = fmaxf(sc1[ic][2 * t], sc1[ic][2 * t + 1]);
    }
    __syncthreads();
    float acc = b2c[tid];
    const float* wrow = w2 + tid * 320;
    const float* cp = &sc1p[0][0];
    #pragma unroll 8
    for (int q = 0; q < 320; q++) acc += cp[q] * wrow[q];
    out[b * OUT_CH + tid] = fmaxf(acc, 0.f);
}

// ---------------- launcher ---------------------------------------------------
extern "C" void kernel_launch(void* const* d_in, const int* in_sizes, int n_in,
                              void* d_out, int out_size)
{
    const float* feats   = (const float*)d_in[0];
    const int*   src     = (const int*)d_in[1];
    const int*   dst     = (const int*)d_in[2];
    const float* W0      = (const float*)d_in[3];
    const float* b0      = (const float*)d_in[4];
    const float* W1      = (const float*)d_in[5];
    const float* b1      = (const float*)d_in[6];
    const float* W2      = (const float*)d_in[7];
    const float* b2      = (const float*)d_in[8];
    const float* conv1_w = (const float*)d_in[9];
    const float* conv1_b = (const float*)d_in[10];
    const float* conv2_w = (const float*)d_in[11];
    const float* conv2_b = (const float*)d_in[12];
    float* out = (float*)d_out;

    int agg_smem  = (256 * KPAD + 2 * 64 * KPAD) * (int)sizeof(__nv_bfloat16);   // 55296
    int gemm_smem = 4 * 128 * KPAD * (int)sizeof(__nv_bfloat16);                 // 73728
    cudaFuncSetAttribute(agg_mma_kernel, cudaFuncAttributeMaxDynamicSharedMemorySize, agg_smem);
    cudaFuncSetAttribute(gemm_bf16_kernel, cudaFuncAttributeMaxDynamicSharedMemorySize, gemm_smem);

    float* bufA;  cudaGetSymbolAddress((void**)&bufA, g_bufA);
    float* bufB;  cudaGetSymbolAddress((void**)&bufB, g_bufB);
    __nv_bfloat16* wthi;  cudaGetSymbolAddress((void**)&wthi, g_Wthi);
    __nv_bfloat16* wtlo;  cudaGetSymbolAddress((void**)&wtlo, g_Wtlo);

    build_kernel<<<BGRAPH, 256>>>(src, dst);
    wsplit_kernel<<<192, 256>>>(W0, W1, W2);

    dim3 agg_grid(BGRAPH, 2);
    // layer 0
    agg_mma_kernel<<<agg_grid, 256, agg_smem>>>(feats, bufA);
    gemm_bf16_kernel<<<NUM_NODES / 128, 256, gemm_smem>>>(bufA, wthi, wtlo, b0, bufB);
    // layer 1
    agg_mma_kernel<<<agg_grid, 256, agg_smem>>>(bufB, bufA);
    gemm_bf16_kernel<<<NUM_NODES / 128, 256, gemm_smem>>>(bufA, wthi + 16384, wtlo + 16384, b1, bufB);
    // layer 2
    agg_mma_kernel<<<agg_grid, 256, agg_smem>>>(bufB, bufA);
    gemm_bf16_kernel<<<NUM_NODES / 128, 256, gemm_smem>>>(bufA, wthi + 32768, wtlo + 32768, b2, bufB);

    key_kernel<<<NUM_NODES / 8, 256>>>();
    topk_kernel<<<BGRAPH / 8, 256>>>();
    sort_rows_kernel<<<BGRAPH * KTOP, 128>>>();
    head_kernel<<<BGRAPH, 128>>>(conv1_w, conv1_b, conv2_w, conv2_b, out);
}